// round 6
// baseline (speedup 1.0000x reference)
#include <cuda_runtime.h>
#include <cstddef>

// ---------------------------------------------------------------------------
// VQ-VAE forward. Convs on tensor pipe via multi-term TF32 mma.sync.m16n8k8.
// fp32 tiles in smem (double-buffered, 1 sync/tile); tf32 h/l split done in
// registers after fragment load (halves LDS traffic).
//   encoder NL=3 (fp32-class, argmin safety), decoder NL=2.
// VQ scores GEMM exact fp32 SIMT. Scratch in __device__ globals.
// ---------------------------------------------------------------------------

#define HS 256
#define NE 512

__device__ __align__(16) float g_h16[16777216];
__device__ __align__(16) float g_h8[4194304];
__device__ __align__(16) float g_t8[4194304];
__device__ __align__(16) float g_q[4194304];
__device__ __align__(16) float g_scores[8388608];
__device__ __align__(16) float g_wp[1048576];
__device__ __align__(16) float g_enorm[512];
__device__ __align__(16) float g_scale[256];
__device__ __align__(16) float g_part[512];

struct GemmP {
    const float* A; const float* W; const float* bias; const float* res; float* out;
    const float* ascale; const float* aweight;
    int N, K;
    int IC, IH, IW, OH, OW, stride, padh, padw;
    int oscale, ooffh, ooffw, oW, oHW;
    int mode;   // 0 plain, 1 bias+relu, 2 res+bias+relu
};

__device__ __forceinline__ unsigned f2tf32(float v) {
    unsigned u;
    asm("cvt.rna.tf32.f32 %0, %1;" : "=r"(u) : "f"(v));
    return u;
}

__device__ __forceinline__ void mma_tf32(float* d, const unsigned* a, const unsigned* b) {
    asm volatile(
        "mma.sync.aligned.m16n8k8.row.col.f32.tf32.tf32.f32 "
        "{%0,%1,%2,%3}, {%4,%5,%6,%7}, {%8,%9}, {%0,%1,%2,%3};"
        : "+f"(d[0]), "+f"(d[1]), "+f"(d[2]), "+f"(d[3])
        : "r"(a[0]), "r"(a[1]), "r"(a[2]), "r"(a[3]), "r"(b[0]), "r"(b[1]));
}

// ---------------------------------------------------------------------------
// Multi-term TF32 conv GEMM: 128x128 CTA, K-tile 16 double-buffered,
// warps 2(m)x4(n) -> 64x32. fp32 smem; h/l split in registers.
// NL=3: ah*bh + al*bh + ah*bl;  NL=2: ah*bh + al*bh.
// ---------------------------------------------------------------------------
template<int KH, int KW, bool RMS, int NL>
__global__ __launch_bounds__(256, 2) void conv_tc(GemmP p) {
    constexpr int KHKW = KH * KW;
    __shared__ float As[2][16 * 136];
    __shared__ float Bs[2][16 * 136];
    __shared__ int sY[128], sX[128], sBase[128], sObase[128];
    __shared__ float sScl[128];

    const int tid = threadIdx.x;
    const int bm = blockIdx.x * 128;
    const int bn = blockIdx.y * 128;

    if (tid < 128) {
        int m = bm + tid;
        int ohw = p.OH * p.OW;
        int n = m / ohw;
        int rem = m - n * ohw;
        int oh = rem / p.OW;
        int ow = rem - oh * p.OW;
        sBase[tid] = n * p.IC * p.IH * p.IW;
        sY[tid] = oh * p.stride - p.padh;
        sX[tid] = ow * p.stride - p.padw;
        sObase[tid] = n * p.N * p.oHW + (oh * p.oscale + p.ooffh) * p.oW
                      + (ow * p.oscale + p.ooffw);
        sScl[tid] = RMS ? p.ascale[n] : 1.f;
    }
    __syncthreads();

    const int IH = p.IH, IW = p.IW;
    const int r = tid & 127;
    const int jset = (tid >> 7) * 8;
    const int rby = sY[r], rbx = sX[r], rbb = sBase[r];
    const float ascl = sScl[r];
    const int nb = tid & 127;
    const int kq = (tid >> 7) * 8;
    const float* Wrow = p.W + (size_t)(bn + nb) * p.K;

    const int w = tid >> 5, lane = tid & 31;
    const int wm = (w & 1) * 64, wn = (w >> 1) * 32;
    const int lg = lane >> 2, lk = lane & 3;

    float acc[4][4][4];
#pragma unroll
    for (int i = 0; i < 4; i++)
#pragma unroll
        for (int j = 0; j < 4; j++)
#pragma unroll
            for (int e = 0; e < 4; e++) acc[i][j][e] = 0.f;

    float avf[8];
    float bvf[8];

    auto gather = [&](int k0) {
#pragma unroll
        for (int q = 0; q < 8; q++) {
            int k = k0 + jset + q;
            int ic = k / KHKW;
            int kk2 = k - ic * KHKW;
            int kh = kk2 / KW;
            int kw = kk2 - kh * KW;
            int ih = rby + kh, iw = rbx + kw;
            float v = 0.f;
            if ((unsigned)ih < (unsigned)IH && (unsigned)iw < (unsigned)IW) {
                int ii = (ic * IH + ih) * IW + iw;
                v = p.A[rbb + ii];
                if (RMS) v *= ascl * p.aweight[ii];
            }
            avf[q] = v;
        }
        float4 b0 = *(const float4*)(Wrow + k0 + kq);
        float4 b1 = *(const float4*)(Wrow + k0 + kq + 4);
        bvf[0] = b0.x; bvf[1] = b0.y; bvf[2] = b0.z; bvf[3] = b0.w;
        bvf[4] = b1.x; bvf[5] = b1.y; bvf[6] = b1.z; bvf[7] = b1.w;
    };
    auto store = [&](int buf) {
#pragma unroll
        for (int q = 0; q < 8; q++) As[buf][(jset + q) * 136 + r] = avf[q];
#pragma unroll
        for (int q = 0; q < 8; q++) Bs[buf][(kq + q) * 136 + nb] = bvf[q];
    };

    const int ntiles = p.K >> 4;
    gather(0);
    store(0);
    __syncthreads();

    for (int t = 0; t < ntiles; t++) {
        const int cur = t & 1;
        if (t + 1 < ntiles) gather((t + 1) << 4);
#pragma unroll
        for (int ks = 0; ks < 2; ks++) {
            const int k0 = ks * 8;
            // B fragments: load fp32, split in regs
            unsigned bfh[4][2], bfl[4][2];
#pragma unroll
            for (int nt = 0; nt < 4; nt++) {
                int nl = wn + nt * 8 + lg;
                float b0 = Bs[cur][(k0 + lk) * 136 + nl];
                float b1 = Bs[cur][(k0 + lk + 4) * 136 + nl];
                bfh[nt][0] = f2tf32(b0);
                bfh[nt][1] = f2tf32(b1);
                if (NL == 3) {
                    bfl[nt][0] = f2tf32(b0 - __uint_as_float(bfh[nt][0]));
                    bfl[nt][1] = f2tf32(b1 - __uint_as_float(bfh[nt][1]));
                }
            }
#pragma unroll
            for (int mt = 0; mt < 4; mt++) {
                int ml = wm + mt * 16 + lg;
                int i0 = (k0 + lk) * 136 + ml;
                int i1 = (k0 + lk + 4) * 136 + ml;
                float a0 = As[cur][i0], a1 = As[cur][i0 + 8];
                float a2 = As[cur][i1], a3 = As[cur][i1 + 8];
                unsigned afh[4], afl[4];
                afh[0] = f2tf32(a0); afh[1] = f2tf32(a1);
                afh[2] = f2tf32(a2); afh[3] = f2tf32(a3);
                afl[0] = f2tf32(a0 - __uint_as_float(afh[0]));
                afl[1] = f2tf32(a1 - __uint_as_float(afh[1]));
                afl[2] = f2tf32(a2 - __uint_as_float(afh[2]));
                afl[3] = f2tf32(a3 - __uint_as_float(afh[3]));
#pragma unroll
                for (int nt = 0; nt < 4; nt++) {
                    mma_tf32(acc[mt][nt], afh, bfh[nt]);
                    mma_tf32(acc[mt][nt], afl, bfh[nt]);
                    if (NL == 3) mma_tf32(acc[mt][nt], afh, bfl[nt]);
                }
            }
        }
        if (t + 1 < ntiles) {
            store(cur ^ 1);
            __syncthreads();
        }
    }

    const int oHW = p.oHW;
#pragma unroll
    for (int mt = 0; mt < 4; mt++) {
#pragma unroll
        for (int half = 0; half < 2; half++) {
            int ml = wm + mt * 16 + lg + half * 8;
            int obase = sObase[ml];
#pragma unroll
            for (int nt = 0; nt < 4; nt++) {
                int oc = bn + wn + nt * 8 + lk * 2;
                float v0 = acc[mt][nt][half * 2 + 0];
                float v1 = acc[mt][nt][half * 2 + 1];
                if (p.bias) { v0 += p.bias[oc]; v1 += p.bias[oc + 1]; }
                if (p.mode >= 1) { v0 = fmaxf(v0, 0.f); v1 = fmaxf(v1, 0.f); }
                size_t oi0 = (size_t)obase + (size_t)oc * oHW;
                size_t oi1 = oi0 + oHW;
                if (p.mode == 2) { v0 += p.res[oi0]; v1 += p.res[oi1]; }
                p.out[oi0] = v0;
                p.out[oi1] = v1;
            }
        }
    }
}

// ---------------------------------------------------------------------------
// Exact fp32 SIMT GEMM (VQ scores, 1x1). 128x128 tile, 8x8/thread.
// ---------------------------------------------------------------------------
__global__ __launch_bounds__(256) void conv_gemm_simt(GemmP p) {
    __shared__ float As[2][16][128];
    __shared__ float Bs[2][16][128];
    __shared__ int sBase[128];

    const int tid = threadIdx.x;
    const int bm = blockIdx.x * 128;
    const int bn = blockIdx.y * 128;

    if (tid < 128) {
        int m = bm + tid;
        int ohw = p.OH * p.OW;
        int n = m / ohw;
        int rem = m - n * ohw;
        sBase[tid] = n * p.IC * p.IH * p.IW + rem;
    }
    __syncthreads();

    const int r = tid & 127;
    const int jset = (tid >> 7) * 8;
    const int rbb = sBase[r];
    const int nb = tid & 127;
    const int kq = (tid >> 7) * 8;
    const float* Wrow = p.W + (size_t)(bn + nb) * p.K;
    const int HWi = p.IH * p.IW;

    float av[8];
    float4 bv0, bv1;
    auto loadAB = [&](int k0) {
#pragma unroll
        for (int q = 0; q < 8; q++) {
            int ic = k0 + jset + q;
            av[q] = p.A[rbb + ic * HWi];
        }
        bv0 = *(const float4*)(Wrow + k0 + kq);
        bv1 = *(const float4*)(Wrow + k0 + kq + 4);
    };
    auto storeAB = [&](int buf) {
#pragma unroll
        for (int q = 0; q < 8; q++) As[buf][jset + q][r] = av[q];
        Bs[buf][kq + 0][nb] = bv0.x; Bs[buf][kq + 1][nb] = bv0.y;
        Bs[buf][kq + 2][nb] = bv0.z; Bs[buf][kq + 3][nb] = bv0.w;
        Bs[buf][kq + 4][nb] = bv1.x; Bs[buf][kq + 5][nb] = bv1.y;
        Bs[buf][kq + 6][nb] = bv1.z; Bs[buf][kq + 7][nb] = bv1.w;
    };

    const int tr = tid >> 4;
    const int tc = tid & 15;
    float acc[8][8];
#pragma unroll
    for (int i = 0; i < 8; i++)
#pragma unroll
        for (int j = 0; j < 8; j++) acc[i][j] = 0.f;

    const int nt = p.K >> 4;
    loadAB(0);
    storeAB(0);
    __syncthreads();
    for (int t = 0; t < nt; t++) {
        const int cur = t & 1;
        if (t + 1 < nt) loadAB((t + 1) << 4);
#pragma unroll
        for (int kk = 0; kk < 16; kk++) {
            float4 a0 = *(const float4*)&As[cur][kk][tr * 8];
            float4 a1 = *(const float4*)&As[cur][kk][tr * 8 + 4];
            float4 b0 = *(const float4*)&Bs[cur][kk][tc * 8];
            float4 b1 = *(const float4*)&Bs[cur][kk][tc * 8 + 4];
            float a[8] = {a0.x, a0.y, a0.z, a0.w, a1.x, a1.y, a1.z, a1.w};
            float b[8] = {b0.x, b0.y, b0.z, b0.w, b1.x, b1.y, b1.z, b1.w};
#pragma unroll
            for (int i = 0; i < 8; i++)
#pragma unroll
                for (int j = 0; j < 8; j++) acc[i][j] += a[i] * b[j];
        }
        if (t + 1 < nt) {
            storeAB(cur ^ 1);
            __syncthreads();
        }
    }

    const int ohw = p.OH * p.OW;
#pragma unroll
    for (int i = 0; i < 8; i++) {
        int m = bm + tr * 8 + i;
        int n = m / ohw;
        int rem = m - n * ohw;
        size_t obase = (size_t)n * p.N * p.oHW + rem;
#pragma unroll
        for (int j = 0; j < 8; j++) {
            int oc = bn + tc * 8 + j;
            p.out[obase + (size_t)oc * p.oHW] = acc[i][j];
        }
    }
}

// ---------------------------------------------------------------------------
__global__ __launch_bounds__(256) void rms_scale_kernel(const float* __restrict__ in,
                                                        float* __restrict__ scale) {
    const int n = blockIdx.x;
    const float4* xp = (const float4*)(in + (size_t)n * 16384);
    float s = 0.f;
    for (int i = threadIdx.x; i < 4096; i += 256) {
        float4 v = xp[i];
        s += v.x * v.x + v.y * v.y + v.z * v.z + v.w * v.w;
    }
    __shared__ float sh[256];
    sh[threadIdx.x] = s;
    __syncthreads();
    for (int st = 128; st > 0; st >>= 1) {
        if (threadIdx.x < st) sh[threadIdx.x] += sh[threadIdx.x + st];
        __syncthreads();
    }
    if (threadIdx.x == 0)
        scale[n] = rsqrtf(sh[0] * (1.f / 16384.f) + 1.1920929e-07f);
}

__global__ void enorm_kernel(const float* __restrict__ e, float* __restrict__ en) {
    int j = blockIdx.x * 256 + threadIdx.x;
    if (j >= NE) return;
    const float* r = e + (size_t)j * HS;
    float s = 0.f;
    for (int c = 0; c < HS; c++) { float v = r[c]; s += v * v; }
    en[j] = s;
}

__global__ __launch_bounds__(256) void vq_argmin_kernel(const float* __restrict__ scores,
                                                        const float* __restrict__ en,
                                                        const float* __restrict__ emb,
                                                        float* __restrict__ q) {
    int token = blockIdx.x * 8 + (threadIdx.x >> 5);
    int lane = threadIdx.x & 31;
    int n = token >> 6, hw = token & 63;
    const float* sc = scores + ((size_t)n * NE) * 64 + hw;
    float best = 3.4e38f;
    int bj = NE;
    for (int j = lane; j < NE; j += 32) {
        float d = en[j] - 2.f * sc[(size_t)j * 64];
        if (d < best || (d == best && j < bj)) { best = d; bj = j; }
    }
#pragma unroll
    for (int off = 16; off; off >>= 1) {
        float ob = __shfl_down_sync(0xffffffffu, best, off);
        int oj = __shfl_down_sync(0xffffffffu, bj, off);
        if (ob < best || (ob == best && oj < bj)) { best = ob; bj = oj; }
    }
    bj = __shfl_sync(0xffffffffu, bj, 0);
    const float* er = emb + (size_t)bj * HS;
    float* qp = q + (size_t)n * HS * 64 + hw;
    for (int c = lane; c < HS; c += 32) qp[(size_t)c * 64] = er[c];
}

__global__ __launch_bounds__(256) void sqdiff_kernel(const float* __restrict__ a,
                                                     const float* __restrict__ b,
                                                     float* __restrict__ part, int nvec4) {
    const float4* a4 = (const float4*)a;
    const float4* b4 = (const float4*)b;
    float s = 0.f;
    for (int i = blockIdx.x * 256 + threadIdx.x; i < nvec4; i += 256 * 256) {
        float4 va = a4[i], vb = b4[i];
        float dx = va.x - vb.x, dy = va.y - vb.y, dz = va.z - vb.z, dw = va.w - vb.w;
        s += dx * dx + dy * dy + dz * dz + dw * dw;
    }
    __shared__ float sh[256];
    sh[threadIdx.x] = s;
    __syncthreads();
    for (int st = 128; st > 0; st >>= 1) {
        if (threadIdx.x < st) sh[threadIdx.x] += sh[threadIdx.x + st];
        __syncthreads();
    }
    if (threadIdx.x == 0) part[blockIdx.x] = sh[0];
}

__global__ void finalize_kernel(const float* __restrict__ partVq,
                                const float* __restrict__ partRec,
                                float* __restrict__ out) {
    if (threadIdx.x == 0 && blockIdx.x == 0) {
        float svq = 0.f, sre = 0.f;
        for (int i = 0; i < 256; i++) { svq += partVq[i]; sre += partRec[i]; }
        float dict = svq * (1.f / 4194304.f);
        float rec = sre * (1.f / 786432.f);
        out[0] = rec + dict + dict;
        out[1] = rec;
        out[2] = dict;
        out[3] = dict;
    }
}

__global__ void prep_wp_kernel(const float* __restrict__ w, float* __restrict__ wp) {
    int idx = blockIdx.x * 256 + threadIdx.x;
    if (idx >= 1048576) return;
    int b = idx & 1;
    int a = (idx >> 1) & 1;
    int ic = (idx >> 2) & 255;
    int oc = (idx >> 10) & 255;
    int p = idx >> 18;
    int ph = p >> 1, pw = p & 1;
    int kh = ph + 2 * a, kw = pw + 2 * b;
    wp[idx] = w[((size_t)(ic * 256 + oc) * 4 + (3 - kh)) * 4 + (3 - kw)];
}

__global__ __launch_bounds__(256) void deconv2_kernel(const float* __restrict__ in,
                                                      const float* __restrict__ w,
                                                      const float* __restrict__ bias,
                                                      float* __restrict__ out) {
    __shared__ float wsh[4 * 256 * 3];
    const int n = blockIdx.x;
    const int par = blockIdx.y;
    const int ph = par >> 1, pw = par & 1;
    const int tid = threadIdx.x;

    for (int idx = tid; idx < 3072; idx += 256) {
        int oc = idx % 3;
        int rest = idx / 3;
        int ic = rest & 255;
        int t = rest >> 8;
        int a = t >> 1, b = t & 1;
        int kh = ph + 2 * a, kw = pw + 2 * b;
        wsh[idx] = w[((size_t)(ic * 3 + oc) * 4 + (3 - kh)) * 4 + (3 - kw)];
    }
    __syncthreads();

    const int i = tid >> 4, j = tid & 15;
    const int oh = 2 * i + ph, ow = 2 * j + pw;
    float acc0 = 0.f, acc1 = 0.f, acc2 = 0.f;

    int base[4];
    bool ok[4];
#pragma unroll
    for (int t = 0; t < 4; t++) {
        int a = t >> 1, b = t & 1;
        int ih = i + ph + a - 1, iw = j + pw + b - 1;
        ok[t] = ((unsigned)ih < 16u) && ((unsigned)iw < 16u);
        base[t] = ok[t] ? (n * 65536 + ih * 16 + iw) : 0;
    }
    for (int ic = 0; ic < 256; ic++) {
        int ico = ic * 256;
#pragma unroll
        for (int t = 0; t < 4; t++) {
            if (ok[t]) {
                float v = in[base[t] + ico];
                const float* wp2 = &wsh[(t * 256 + ic) * 3];
                acc0 += v * wp2[0];
                acc1 += v * wp2[1];
                acc2 += v * wp2[2];
            }
        }
    }
    size_t o = (size_t)n * 3072 + (size_t)oh * 32 + ow;
    out[o] = acc0 + bias[0];
    out[o + 1024] = acc1 + bias[1];
    out[o + 2048] = acc2 + bias[2];
}

// ---------------------------------------------------------------------------
static GemmP mkP(const float* A, const float* W, const float* bias, const float* res,
                 float* out, const float* ascale, const float* aweight,
                 int N, int K, int IC, int IH, int IW, int OH, int OW,
                 int stride, int padh, int padw,
                 int oscale, int ooffh, int ooffw, int oW, int oHW, int mode) {
    GemmP p;
    p.A = A; p.W = W; p.bias = bias; p.res = res; p.out = out;
    p.ascale = ascale; p.aweight = aweight;
    p.N = N; p.K = K; p.IC = IC; p.IH = IH; p.IW = IW; p.OH = OH; p.OW = OW;
    p.stride = stride; p.padh = padh; p.padw = padw;
    p.oscale = oscale; p.ooffh = ooffh; p.ooffw = ooffw; p.oW = oW; p.oHW = oHW;
    p.mode = mode;
    return p;
}

template<int NL>
static void res_block(float* x, float* tmp, float* scl, const float* rmsw,
                      const float* w3, const float* b3,
                      const float* w1, const float* b1) {
    rms_scale_kernel<<<256, 256>>>(x, scl);
    {
        GemmP p = mkP(x, w3, b3, x, tmp, scl, rmsw,
                      256, 2304, 256, 8, 8, 8, 8, 1, 1, 1,
                      1, 0, 0, 8, 64, 2);
        conv_tc<3, 3, true, NL><<<dim3(128, 2), 256>>>(p);
    }
    rms_scale_kernel<<<256, 256>>>(tmp, scl);
    {
        GemmP p = mkP(tmp, w1, b1, tmp, x, scl, rmsw + 16384,
                      256, 256, 256, 8, 8, 8, 8, 1, 0, 0,
                      1, 0, 0, 8, 64, 2);
        conv_tc<1, 1, true, NL><<<dim3(128, 2), 256>>>(p);
    }
}

extern "C" void kernel_launch(void* const* d_in, const int* in_sizes, int n_in,
                              void* d_out, int out_size) {
    const float* x       = (const float*)d_in[0];
    const float* enc_w1  = (const float*)d_in[1];
    const float* enc_b1  = (const float*)d_in[2];
    const float* enc_w2  = (const float*)d_in[3];
    const float* enc_b2  = (const float*)d_in[4];
    const float* rms_w   = (const float*)d_in[5];
    const float* c3_w    = (const float*)d_in[6];
    const float* c3_b    = (const float*)d_in[7];
    const float* c1_w    = (const float*)d_in[8];
    const float* c1_b    = (const float*)d_in[9];
    const float* emb     = (const float*)d_in[10];
    const float* dec_w1  = (const float*)d_in[11];
    const float* dec_b1  = (const float*)d_in[12];
    const float* dec_w2  = (const float*)d_in[13];
    const float* dec_b2  = (const float*)d_in[14];
    float* out = (float*)d_out;

    float *h16, *h8, *t8, *q, *scores, *wp, *en, *scl, *part;
    cudaGetSymbolAddress((void**)&h16, g_h16);
    cudaGetSymbolAddress((void**)&h8, g_h8);
    cudaGetSymbolAddress((void**)&t8, g_t8);
    cudaGetSymbolAddress((void**)&q, g_q);
    cudaGetSymbolAddress((void**)&scores, g_scores);
    cudaGetSymbolAddress((void**)&wp, g_wp);
    cudaGetSymbolAddress((void**)&en, g_enorm);
    cudaGetSymbolAddress((void**)&scl, g_scale);
    cudaGetSymbolAddress((void**)&part, g_part);

    // ---- Encoder (3-term TF32: protects VQ argmin) ----
    {
        GemmP p = mkP(x, enc_w1, enc_b1, nullptr, h16, nullptr, nullptr,
                      256, 48, 3, 32, 32, 16, 16, 2, 1, 1,
                      1, 0, 0, 16, 256, 1);
        conv_tc<4, 4, false, 3><<<dim3(512, 2), 256>>>(p);
    }
    {
        GemmP p = mkP(h16, enc_w2, enc_b2, nullptr, h8, nullptr, nullptr,
                      256, 4096, 256, 16, 16, 8, 8, 2, 1, 1,
                      1, 0, 0, 8, 64, 1);
        conv_tc<4, 4, false, 3><<<dim3(128, 2), 256>>>(p);
    }
    res_block<3>(h8, t8, scl, rms_w + 0 * 32768, c3_w + 0 * 589824, c3_b + 0 * 256,
                 c1_w + 0 * 65536, c1_b + 0 * 256);
    res_block<3>(h8, t8, scl, rms_w + 1 * 32768, c3_w + 1 * 589824, c3_b + 1 * 256,
                 c1_w + 1 * 65536, c1_b + 1 * 256);

    // ---- VQ (exact fp32 scores) ----
    enorm_kernel<<<2, 256>>>(emb, en);
    {
        GemmP p = mkP(h8, emb, nullptr, nullptr, scores, nullptr, nullptr,
                      512, 256, 256, 8, 8, 8, 8, 1, 0, 0,
                      1, 0, 0, 8, 64, 0);
        conv_gemm_simt<<<dim3(128, 4), 256>>>(p);
    }
    vq_argmin_kernel<<<2048, 256>>>(scores, en, emb, q);
    sqdiff_kernel<<<256, 256>>>(h8, q, part, 1048576);

    // ---- Decoder (2-term TF32: post-argmin) ----
    res_block<2>(q, t8, scl, rms_w + 2 * 32768, c3_w + 2 * 589824, c3_b + 2 * 256,
                 c1_w + 2 * 65536, c1_b + 2 * 256);
    res_block<2>(q, t8, scl, rms_w + 3 * 32768, c3_w + 3 * 589824, c3_b + 3 * 256,
                 c1_w + 3 * 65536, c1_b + 3 * 256);

    prep_wp_kernel<<<4096, 256>>>(dec_w1, wp);
    for (int par = 0; par < 4; par++) {
        int ph = par >> 1, pw = par & 1;
        GemmP p = mkP(q, wp + (size_t)par * 262144, dec_b1, nullptr, h16, nullptr, nullptr,
                      256, 1024, 256, 8, 8, 8, 8, 1, 1 - ph, 1 - pw,
                      2, ph, pw, 16, 256, 1);
        conv_tc<2, 2, false, 2><<<dim3(128, 2), 256>>>(p);
    }

    deconv2_kernel<<<dim3(256, 4), 256>>>(h16, dec_w2, dec_b2, out + 4);

    sqdiff_kernel<<<256, 256>>>(out + 4, x, part + 256, 196608);
    finalize_kernel<<<1, 32>>>(part, part + 256, out);
}

// round 7
// speedup vs baseline: 1.1064x; 1.1064x over previous
#include <cuda_runtime.h>
#include <cstddef>

// ---------------------------------------------------------------------------
// VQ-VAE forward. Convs via multi-term TF32 mma.sync.m16n8k8.
// CTA tile 128x256, 8 warps as 2m x 4n -> 64x64 warp tile (crossbar-optimal).
// h/l split once at store; dynamic smem 100KB double-buffered, 1 sync/tile.
// encoder NL=3 (fp32-class, argmin safety), decoder NL=2.
// VQ scores GEMM exact fp32 SIMT. Scratch in __device__ globals.
// ---------------------------------------------------------------------------

#define HS 256
#define NE 512

__device__ __align__(16) float g_h16[16777216];
__device__ __align__(16) float g_h8[4194304];
__device__ __align__(16) float g_t8[4194304];
__device__ __align__(16) float g_q[4194304];
__device__ __align__(16) float g_scores[8388608];
__device__ __align__(16) float g_wp[1048576];
__device__ __align__(16) float g_enorm[512];
__device__ __align__(16) float g_scale[256];
__device__ __align__(16) float g_part[512];

struct GemmP {
    const float* A; const float* W; const float* bias; const float* res; float* out;
    const float* ascale; const float* aweight;
    int N, K;
    int IC, IH, IW, OH, OW, stride, padh, padw;
    int oscale, ooffh, ooffw, oW, oHW;
    int mode;   // 0 plain, 1 bias+relu, 2 res+bias+relu
};

__device__ __forceinline__ unsigned f2tf32(float v) {
    unsigned u;
    asm("cvt.rna.tf32.f32 %0, %1;" : "=r"(u) : "f"(v));
    return u;
}

__device__ __forceinline__ void mma_tf32(float* d, const unsigned* a, const unsigned* b) {
    asm volatile(
        "mma.sync.aligned.m16n8k8.row.col.f32.tf32.tf32.f32 "
        "{%0,%1,%2,%3}, {%4,%5,%6,%7}, {%8,%9}, {%0,%1,%2,%3};"
        : "+f"(d[0]), "+f"(d[1]), "+f"(d[2]), "+f"(d[3])
        : "r"(a[0]), "r"(a[1]), "r"(a[2]), "r"(a[3]), "r"(b[0]), "r"(b[1]));
}

// smem layout (floats), per buffer: Ah[16*136] Al[16*136] Bh[16*264] Bl[16*264]
#define A_STR 136
#define B_STR 264
#define BUF_FLOATS (2 * 16 * A_STR + 2 * 16 * B_STR)   // 12800
#define SMEM_BYTES (2 * BUF_FLOATS * 4)                 // 102400

// ---------------------------------------------------------------------------
// Multi-term TF32 conv GEMM: CTA 128x256, K-tile 16 double-buffered,
// 8 warps 2(m) x 4(n) -> 64x64 each. NL=3: +al*bh +ah*bl; NL=2: +al*bh.
// ---------------------------------------------------------------------------
template<int KH, int KW, bool RMS, int NL>
__global__ __launch_bounds__(256, 1) void conv_tc(GemmP p) {
    constexpr int KHKW = KH * KW;
    extern __shared__ float smem[];
    __shared__ int sY[128], sX[128], sBase[128], sObase[128];
    __shared__ float sScl[128];

    const int tid = threadIdx.x;
    const int bm = blockIdx.x * 128;
    const int bn = blockIdx.y * 256;

    if (tid < 128) {
        int m = bm + tid;
        int ohw = p.OH * p.OW;
        int n = m / ohw;
        int rem = m - n * ohw;
        int oh = rem / p.OW;
        int ow = rem - oh * p.OW;
        sBase[tid] = n * p.IC * p.IH * p.IW;
        sY[tid] = oh * p.stride - p.padh;
        sX[tid] = ow * p.stride - p.padw;
        sObase[tid] = n * p.N * p.oHW + (oh * p.oscale + p.ooffh) * p.oW
                      + (ow * p.oscale + p.ooffw);
        sScl[tid] = RMS ? p.ascale[n] : 1.f;
    }
    __syncthreads();

    const int IH = p.IH, IW = p.IW;
    // A-gather role: 128 rows x 16 k, thread -> (r, 8 k)
    const int r = tid & 127;
    const int jset = (tid >> 7) * 8;
    const int rby = sY[r], rbx = sX[r], rbb = sBase[r];
    const float ascl = sScl[r];
    // B-gather role: 256 rows (n) x 16 k, thread -> (nb, 16 k)
    const int nb = tid;
    const float* Wrow = p.W + (size_t)(bn + nb) * p.K;

    // warp roles: 2m x 4n, warp tile 64x64
    const int w = tid >> 5, lane = tid & 31;
    const int wm = (w & 1) * 64, wn = (w >> 1) * 64;
    const int lg = lane >> 2, lk = lane & 3;

    float acc[4][8][4];
#pragma unroll
    for (int i = 0; i < 4; i++)
#pragma unroll
        for (int j = 0; j < 8; j++)
#pragma unroll
            for (int e = 0; e < 4; e++) acc[i][j][e] = 0.f;

    float avf[8];
    float bvf[16];

    auto gather = [&](int k0) {
#pragma unroll
        for (int q = 0; q < 8; q++) {
            int k = k0 + jset + q;
            int ic = k / KHKW;
            int kk2 = k - ic * KHKW;
            int kh = kk2 / KW;
            int kw = kk2 - kh * KW;
            int ih = rby + kh, iw = rbx + kw;
            float v = 0.f;
            if ((unsigned)ih < (unsigned)IH && (unsigned)iw < (unsigned)IW) {
                int ii = (ic * IH + ih) * IW + iw;
                v = p.A[rbb + ii];
                if (RMS) v *= ascl * p.aweight[ii];
            }
            avf[q] = v;
        }
#pragma unroll
        for (int q4 = 0; q4 < 4; q4++) {
            float4 b = *(const float4*)(Wrow + k0 + q4 * 4);
            bvf[q4 * 4 + 0] = b.x; bvf[q4 * 4 + 1] = b.y;
            bvf[q4 * 4 + 2] = b.z; bvf[q4 * 4 + 3] = b.w;
        }
    };
    auto store = [&](int buf) {
        float* Ah = smem + buf * BUF_FLOATS;
        float* Al = Ah + 16 * A_STR;
        float* Bh = Al + 16 * A_STR;
        float* Bl = Bh + 16 * B_STR;
#pragma unroll
        for (int q = 0; q < 8; q++) {
            unsigned h = f2tf32(avf[q]);
            Ah[(jset + q) * A_STR + r] = __uint_as_float(h);
            Al[(jset + q) * A_STR + r] = avf[q] - __uint_as_float(h);
        }
#pragma unroll
        for (int k = 0; k < 16; k++) {
            unsigned h = f2tf32(bvf[k]);
            Bh[k * B_STR + nb] = __uint_as_float(h);
            if (NL == 3) Bl[k * B_STR + nb] = bvf[k] - __uint_as_float(h);
        }
    };

    const int ntiles = p.K >> 4;
    gather(0);
    store(0);
    __syncthreads();

    for (int t = 0; t < ntiles; t++) {
        const int cur = t & 1;
        const float* Ah = smem + cur * BUF_FLOATS;
        const float* Al = Ah + 16 * A_STR;
        const float* Bh = Al + 16 * A_STR;
        const float* Bl = Bh + 16 * B_STR;
        if (t + 1 < ntiles) gather((t + 1) << 4);
#pragma unroll
        for (int ks = 0; ks < 2; ks++) {
            const int k0 = ks * 8;
            unsigned bfh[8][2], bfl[8][2];
#pragma unroll
            for (int nt = 0; nt < 8; nt++) {
                int nl = wn + nt * 8 + lg;
                bfh[nt][0] = __float_as_uint(Bh[(k0 + lk) * B_STR + nl]);
                bfh[nt][1] = __float_as_uint(Bh[(k0 + lk + 4) * B_STR + nl]);
                if (NL == 3) {
                    bfl[nt][0] = f2tf32(Bl[(k0 + lk) * B_STR + nl]);
                    bfl[nt][1] = f2tf32(Bl[(k0 + lk + 4) * B_STR + nl]);
                }
            }
#pragma unroll
            for (int mt = 0; mt < 4; mt++) {
                int ml = wm + mt * 16 + lg;
                int i0 = (k0 + lk) * A_STR + ml;
                int i1 = (k0 + lk + 4) * A_STR + ml;
                unsigned afh[4], afl[4];
                afh[0] = __float_as_uint(Ah[i0]);
                afh[1] = __float_as_uint(Ah[i0 + 8]);
                afh[2] = __float_as_uint(Ah[i1]);
                afh[3] = __float_as_uint(Ah[i1 + 8]);
                afl[0] = f2tf32(Al[i0]);
                afl[1] = f2tf32(Al[i0 + 8]);
                afl[2] = f2tf32(Al[i1]);
                afl[3] = f2tf32(Al[i1 + 8]);
#pragma unroll
                for (int nt = 0; nt < 8; nt++) {
                    mma_tf32(acc[mt][nt], afh, bfh[nt]);
                    mma_tf32(acc[mt][nt], afl, bfh[nt]);
                    if (NL == 3) mma_tf32(acc[mt][nt], afh, bfl[nt]);
                }
            }
        }
        if (t + 1 < ntiles) {
            store(cur ^ 1);
            __syncthreads();
        }
    }

    const int oHW = p.oHW;
#pragma unroll
    for (int mt = 0; mt < 4; mt++) {
#pragma unroll
        for (int half = 0; half < 2; half++) {
            int ml = wm + mt * 16 + lg + half * 8;
            int obase = sObase[ml];
#pragma unroll
            for (int nt = 0; nt < 8; nt++) {
                int oc = bn + wn + nt * 8 + lk * 2;
                float v0 = acc[mt][nt][half * 2 + 0];
                float v1 = acc[mt][nt][half * 2 + 1];
                if (p.bias) { v0 += p.bias[oc]; v1 += p.bias[oc + 1]; }
                if (p.mode >= 1) { v0 = fmaxf(v0, 0.f); v1 = fmaxf(v1, 0.f); }
                size_t oi0 = (size_t)obase + (size_t)oc * oHW;
                size_t oi1 = oi0 + oHW;
                if (p.mode == 2) { v0 += p.res[oi0]; v1 += p.res[oi1]; }
                p.out[oi0] = v0;
                p.out[oi1] = v1;
            }
        }
    }
}

// ---------------------------------------------------------------------------
// Exact fp32 SIMT GEMM (VQ scores, 1x1). 128x128 tile, 8x8/thread.
// ---------------------------------------------------------------------------
__global__ __launch_bounds__(256) void conv_gemm_simt(GemmP p) {
    __shared__ float As[2][16][128];
    __shared__ float Bs[2][16][128];
    __shared__ int sBase[128];

    const int tid = threadIdx.x;
    const int bm = blockIdx.x * 128;
    const int bn = blockIdx.y * 128;

    if (tid < 128) {
        int m = bm + tid;
        int ohw = p.OH * p.OW;
        int n = m / ohw;
        int rem = m - n * ohw;
        sBase[tid] = n * p.IC * p.IH * p.IW + rem;
    }
    __syncthreads();

    const int r = tid & 127;
    const int jset = (tid >> 7) * 8;
    const int rbb = sBase[r];
    const int nb = tid & 127;
    const int kq = (tid >> 7) * 8;
    const float* Wrow = p.W + (size_t)(bn + nb) * p.K;
    const int HWi = p.IH * p.IW;

    float av[8];
    float4 bv0, bv1;
    auto loadAB = [&](int k0) {
#pragma unroll
        for (int q = 0; q < 8; q++) {
            int ic = k0 + jset + q;
            av[q] = p.A[rbb + ic * HWi];
        }
        bv0 = *(const float4*)(Wrow + k0 + kq);
        bv1 = *(const float4*)(Wrow + k0 + kq + 4);
    };
    auto storeAB = [&](int buf) {
#pragma unroll
        for (int q = 0; q < 8; q++) As[buf][jset + q][r] = av[q];
        Bs[buf][kq + 0][nb] = bv0.x; Bs[buf][kq + 1][nb] = bv0.y;
        Bs[buf][kq + 2][nb] = bv0.z; Bs[buf][kq + 3][nb] = bv0.w;
        Bs[buf][kq + 4][nb] = bv1.x; Bs[buf][kq + 5][nb] = bv1.y;
        Bs[buf][kq + 6][nb] = bv1.z; Bs[buf][kq + 7][nb] = bv1.w;
    };

    const int tr = tid >> 4;
    const int tc = tid & 15;
    float acc[8][8];
#pragma unroll
    for (int i = 0; i < 8; i++)
#pragma unroll
        for (int j = 0; j < 8; j++) acc[i][j] = 0.f;

    const int nt = p.K >> 4;
    loadAB(0);
    storeAB(0);
    __syncthreads();
    for (int t = 0; t < nt; t++) {
        const int cur = t & 1;
        if (t + 1 < nt) loadAB((t + 1) << 4);
#pragma unroll
        for (int kk = 0; kk < 16; kk++) {
            float4 a0 = *(const float4*)&As[cur][kk][tr * 8];
            float4 a1 = *(const float4*)&As[cur][kk][tr * 8 + 4];
            float4 b0 = *(const float4*)&Bs[cur][kk][tc * 8];
            float4 b1 = *(const float4*)&Bs[cur][kk][tc * 8 + 4];
            float a[8] = {a0.x, a0.y, a0.z, a0.w, a1.x, a1.y, a1.z, a1.w};
            float b[8] = {b0.x, b0.y, b0.z, b0.w, b1.x, b1.y, b1.z, b1.w};
#pragma unroll
            for (int i = 0; i < 8; i++)
#pragma unroll
                for (int j = 0; j < 8; j++) acc[i][j] += a[i] * b[j];
        }
        if (t + 1 < nt) {
            storeAB(cur ^ 1);
            __syncthreads();
        }
    }

    const int ohw = p.OH * p.OW;
#pragma unroll
    for (int i = 0; i < 8; i++) {
        int m = bm + tr * 8 + i;
        int n = m / ohw;
        int rem = m - n * ohw;
        size_t obase = (size_t)n * p.N * p.oHW + rem;
#pragma unroll
        for (int j = 0; j < 8; j++) {
            int oc = bn + tc * 8 + j;
            p.out[obase + (size_t)oc * p.oHW] = acc[i][j];
        }
    }
}

// ---------------------------------------------------------------------------
__global__ __launch_bounds__(256) void rms_scale_kernel(const float* __restrict__ in,
                                                        float* __restrict__ scale) {
    const int n = blockIdx.x;
    const float4* xp = (const float4*)(in + (size_t)n * 16384);
    float s = 0.f;
    for (int i = threadIdx.x; i < 4096; i += 256) {
        float4 v = xp[i];
        s += v.x * v.x + v.y * v.y + v.z * v.z + v.w * v.w;
    }
    __shared__ float sh[256];
    sh[threadIdx.x] = s;
    __syncthreads();
    for (int st = 128; st > 0; st >>= 1) {
        if (threadIdx.x < st) sh[threadIdx.x] += sh[threadIdx.x + st];
        __syncthreads();
    }
    if (threadIdx.x == 0)
        scale[n] = rsqrtf(sh[0] * (1.f / 16384.f) + 1.1920929e-07f);
}

__global__ void enorm_kernel(const float* __restrict__ e, float* __restrict__ en) {
    int j = blockIdx.x * 256 + threadIdx.x;
    if (j >= NE) return;
    const float* r = e + (size_t)j * HS;
    float s = 0.f;
    for (int c = 0; c < HS; c++) { float v = r[c]; s += v * v; }
    en[j] = s;
}

__global__ __launch_bounds__(256) void vq_argmin_kernel(const float* __restrict__ scores,
                                                        const float* __restrict__ en,
                                                        const float* __restrict__ emb,
                                                        float* __restrict__ q) {
    int token = blockIdx.x * 8 + (threadIdx.x >> 5);
    int lane = threadIdx.x & 31;
    int n = token >> 6, hw = token & 63;
    const float* sc = scores + ((size_t)n * NE) * 64 + hw;
    float best = 3.4e38f;
    int bj = NE;
    for (int j = lane; j < NE; j += 32) {
        float d = en[j] - 2.f * sc[(size_t)j * 64];
        if (d < best || (d == best && j < bj)) { best = d; bj = j; }
    }
#pragma unroll
    for (int off = 16; off; off >>= 1) {
        float ob = __shfl_down_sync(0xffffffffu, best, off);
        int oj = __shfl_down_sync(0xffffffffu, bj, off);
        if (ob < best || (ob == best && oj < bj)) { best = ob; bj = oj; }
    }
    bj = __shfl_sync(0xffffffffu, bj, 0);
    const float* er = emb + (size_t)bj * HS;
    float* qp = q + (size_t)n * HS * 64 + hw;
    for (int c = lane; c < HS; c += 32) qp[(size_t)c * 64] = er[c];
}

__global__ __launch_bounds__(256) void sqdiff_kernel(const float* __restrict__ a,
                                                     const float* __restrict__ b,
                                                     float* __restrict__ part, int nvec4) {
    const float4* a4 = (const float4*)a;
    const float4* b4 = (const float4*)b;
    float s = 0.f;
    for (int i = blockIdx.x * 256 + threadIdx.x; i < nvec4; i += 256 * 256) {
        float4 va = a4[i], vb = b4[i];
        float dx = va.x - vb.x, dy = va.y - vb.y, dz = va.z - vb.z, dw = va.w - vb.w;
        s += dx * dx + dy * dy + dz * dz + dw * dw;
    }
    __shared__ float sh[256];
    sh[threadIdx.x] = s;
    __syncthreads();
    for (int st = 128; st > 0; st >>= 1) {
        if (threadIdx.x < st) sh[threadIdx.x] += sh[threadIdx.x + st];
        __syncthreads();
    }
    if (threadIdx.x == 0) part[blockIdx.x] = sh[0];
}

__global__ void finalize_kernel(const float* __restrict__ partVq,
                                const float* __restrict__ partRec,
                                float* __restrict__ out) {
    if (threadIdx.x == 0 && blockIdx.x == 0) {
        float svq = 0.f, sre = 0.f;
        for (int i = 0; i < 256; i++) { svq += partVq[i]; sre += partRec[i]; }
        float dict = svq * (1.f / 4194304.f);
        float rec = sre * (1.f / 786432.f);
        out[0] = rec + dict + dict;
        out[1] = rec;
        out[2] = dict;
        out[3] = dict;
    }
}

__global__ void prep_wp_kernel(const float* __restrict__ w, float* __restrict__ wp) {
    int idx = blockIdx.x * 256 + threadIdx.x;
    if (idx >= 1048576) return;
    int b = idx & 1;
    int a = (idx >> 1) & 1;
    int ic = (idx >> 2) & 255;
    int oc = (idx >> 10) & 255;
    int p = idx >> 18;
    int ph = p >> 1, pw = p & 1;
    int kh = ph + 2 * a, kw = pw + 2 * b;
    wp[idx] = w[((size_t)(ic * 256 + oc) * 4 + (3 - kh)) * 4 + (3 - kw)];
}

__global__ __launch_bounds__(256) void deconv2_kernel(const float* __restrict__ in,
                                                      const float* __restrict__ w,
                                                      const float* __restrict__ bias,
                                                      float* __restrict__ out) {
    __shared__ float wsh[4 * 256 * 3];
    const int n = blockIdx.x;
    const int par = blockIdx.y;
    const int ph = par >> 1, pw = par & 1;
    const int tid = threadIdx.x;

    for (int idx = tid; idx < 3072; idx += 256) {
        int oc = idx % 3;
        int rest = idx / 3;
        int ic = rest & 255;
        int t = rest >> 8;
        int a = t >> 1, b = t & 1;
        int kh = ph + 2 * a, kw = pw + 2 * b;
        wsh[idx] = w[((size_t)(ic * 3 + oc) * 4 + (3 - kh)) * 4 + (3 - kw)];
    }
    __syncthreads();

    const int i = tid >> 4, j = tid & 15;
    const int oh = 2 * i + ph, ow = 2 * j + pw;
    float acc0 = 0.f, acc1 = 0.f, acc2 = 0.f;

    int base[4];
    bool ok[4];
#pragma unroll
    for (int t = 0; t < 4; t++) {
        int a = t >> 1, b = t & 1;
        int ih = i + ph + a - 1, iw = j + pw + b - 1;
        ok[t] = ((unsigned)ih < 16u) && ((unsigned)iw < 16u);
        base[t] = ok[t] ? (n * 65536 + ih * 16 + iw) : 0;
    }
    for (int ic = 0; ic < 256; ic++) {
        int ico = ic * 256;
#pragma unroll
        for (int t = 0; t < 4; t++) {
            if (ok[t]) {
                float v = in[base[t] + ico];
                const float* wp2 = &wsh[(t * 256 + ic) * 3];
                acc0 += v * wp2[0];
                acc1 += v * wp2[1];
                acc2 += v * wp2[2];
            }
        }
    }
    size_t o = (size_t)n * 3072 + (size_t)oh * 32 + ow;
    out[o] = acc0 + bias[0];
    out[o + 1024] = acc1 + bias[1];
    out[o + 2048] = acc2 + bias[2];
}

// ---------------------------------------------------------------------------
static GemmP mkP(const float* A, const float* W, const float* bias, const float* res,
                 float* out, const float* ascale, const float* aweight,
                 int N, int K, int IC, int IH, int IW, int OH, int OW,
                 int stride, int padh, int padw,
                 int oscale, int ooffh, int ooffw, int oW, int oHW, int mode) {
    GemmP p;
    p.A = A; p.W = W; p.bias = bias; p.res = res; p.out = out;
    p.ascale = ascale; p.aweight = aweight;
    p.N = N; p.K = K; p.IC = IC; p.IH = IH; p.IW = IW; p.OH = OH; p.OW = OW;
    p.stride = stride; p.padh = padh; p.padw = padw;
    p.oscale = oscale; p.ooffh = ooffh; p.ooffw = ooffw; p.oW = oW; p.oHW = oHW;
    p.mode = mode;
    return p;
}

template<int KH, int KW, bool RMS, int NL>
static void launch_tc(GemmP p, int M) {
    cudaFuncSetAttribute(conv_tc<KH, KW, RMS, NL>,
                         cudaFuncAttributeMaxDynamicSharedMemorySize, SMEM_BYTES);
    dim3 g(M / 128, p.N / 256);
    conv_tc<KH, KW, RMS, NL><<<g, 256, SMEM_BYTES>>>(p);
}

template<int NL>
static void res_block(float* x, float* tmp, float* scl, const float* rmsw,
                      const float* w3, const float* b3,
                      const float* w1, const float* b1) {
    rms_scale_kernel<<<256, 256>>>(x, scl);
    {
        GemmP p = mkP(x, w3, b3, x, tmp, scl, rmsw,
                      256, 2304, 256, 8, 8, 8, 8, 1, 1, 1,
                      1, 0, 0, 8, 64, 2);
        launch_tc<3, 3, true, NL>(p, 16384);
    }
    rms_scale_kernel<<<256, 256>>>(tmp, scl);
    {
        GemmP p = mkP(tmp, w1, b1, tmp, x, scl, rmsw + 16384,
                      256, 256, 256, 8, 8, 8, 8, 1, 0, 0,
                      1, 0, 0, 8, 64, 2);
        launch_tc<1, 1, true, NL>(p, 16384);
    }
}

extern "C" void kernel_launch(void* const* d_in, const int* in_sizes, int n_in,
                              void* d_out, int out_size) {
    const float* x       = (const float*)d_in[0];
    const float* enc_w1  = (const float*)d_in[1];
    const float* enc_b1  = (const float*)d_in[2];
    const float* enc_w2  = (const float*)d_in[3];
    const float* enc_b2  = (const float*)d_in[4];
    const float* rms_w   = (const float*)d_in[5];
    const float* c3_w    = (const float*)d_in[6];
    const float* c3_b    = (const float*)d_in[7];
    const float* c1_w    = (const float*)d_in[8];
    const float* c1_b    = (const float*)d_in[9];
    const float* emb     = (const float*)d_in[10];
    const float* dec_w1  = (const float*)d_in[11];
    const float* dec_b1  = (const float*)d_in[12];
    const float* dec_w2  = (const float*)d_in[13];
    const float* dec_b2  = (const float*)d_in[14];
    float* out = (float*)d_out;

    float *h16, *h8, *t8, *q, *scores, *wp, *en, *scl, *part;
    cudaGetSymbolAddress((void**)&h16, g_h16);
    cudaGetSymbolAddress((void**)&h8, g_h8);
    cudaGetSymbolAddress((void**)&t8, g_t8);
    cudaGetSymbolAddress((void**)&q, g_q);
    cudaGetSymbolAddress((void**)&scores, g_scores);
    cudaGetSymbolAddress((void**)&wp, g_wp);
    cudaGetSymbolAddress((void**)&en, g_enorm);
    cudaGetSymbolAddress((void**)&scl, g_scale);
    cudaGetSymbolAddress((void**)&part, g_part);

    // ---- Encoder (3-term TF32: protects VQ argmin) ----
    {
        GemmP p = mkP(x, enc_w1, enc_b1, nullptr, h16, nullptr, nullptr,
                      256, 48, 3, 32, 32, 16, 16, 2, 1, 1,
                      1, 0, 0, 16, 256, 1);
        launch_tc<4, 4, false, 3>(p, 65536);
    }
    {
        GemmP p = mkP(h16, enc_w2, enc_b2, nullptr, h8, nullptr, nullptr,
                      256, 4096, 256, 16, 16, 8, 8, 2, 1, 1,
                      1, 0, 0, 8, 64, 1);
        launch_tc<4, 4, false, 3>(p, 16384);
    }
    res_block<3>(h8, t8, scl, rms_w + 0 * 32768, c3_w + 0 * 589824, c3_b + 0 * 256,
                 c1_w + 0 * 65536, c1_b + 0 * 256);
    res_block<3>(h8, t8, scl, rms_w + 1 * 32768, c3_w + 1 * 589824, c3_b + 1 * 256,
                 c1_w + 1 * 65536, c1_b + 1 * 256);

    // ---- VQ (exact fp32 scores) ----
    enorm_kernel<<<2, 256>>>(emb, en);
    {
        GemmP p = mkP(h8, emb, nullptr, nullptr, scores, nullptr, nullptr,
                      512, 256, 256, 8, 8, 8, 8, 1, 0, 0,
                      1, 0, 0, 8, 64, 0);
        conv_gemm_simt<<<dim3(128, 4), 256>>>(p);
    }
    vq_argmin_kernel<<<2048, 256>>>(scores, en, emb, q);
    sqdiff_kernel<<<256, 256>>>(h8, q, part, 1048576);

    // ---- Decoder (2-term TF32: post-argmin) ----
    res_block<2>(q, t8, scl, rms_w + 2 * 32768, c3_w + 2 * 589824, c3_b + 2 * 256,
                 c1_w + 2 * 65536, c1_b + 2 * 256);
    res_block<2>(q, t8, scl, rms_w + 3 * 32768, c3_w + 3 * 589824, c3_b + 3 * 256,
                 c1_w + 3 * 65536, c1_b + 3 * 256);

    prep_wp_kernel<<<4096, 256>>>(dec_w1, wp);
    for (int par = 0; par < 4; par++) {
        int ph = par >> 1, pw = par & 1;
        GemmP p = mkP(q, wp + (size_t)par * 262144, dec_b1, nullptr, h16, nullptr, nullptr,
                      256, 1024, 256, 8, 8, 8, 8, 1, 1 - ph, 1 - pw,
                      2, ph, pw, 16, 256, 1);
        launch_tc<2, 2, false, 2>(p, 16384);
    }

    deconv2_kernel<<<dim3(256, 4), 256>>>(h16, dec_w2, dec_b2, out + 4);

    sqdiff_kernel<<<256, 256>>>(out + 4, x, part + 256, 196608);
    finalize_kernel<<<1, 32>>>(part, part + 256, out);
}

// round 9
// speedup vs baseline: 1.4458x; 1.3068x over previous
#include <cuda_runtime.h>
#include <cstddef>
#include <cstdint>

// ---------------------------------------------------------------------------
// VQ-VAE forward. Convs via bf16x3 emulated-fp32 mma.sync.m16n8k16
// (a=ah+al, b=bh+bl in bf16; acc += ah*bh + al*bh + ah*bl; error ~2^-18).
// CTA tile 128x256, 8 warps 2m x 4n -> 64x64 warp tile, K-tile 16,
// double-buffered packed-bf16x2 smem, 1 sync/tile.
// VQ scores GEMM exact fp32 SIMT. Scratch in __device__ globals.
// ---------------------------------------------------------------------------

#define HS 256
#define NE 512

__device__ __align__(16) float g_h16[16777216];
__device__ __align__(16) float g_h8[4194304];
__device__ __align__(16) float g_t8[4194304];
__device__ __align__(16) float g_q[4194304];
__device__ __align__(16) float g_scores[8388608];
__device__ __align__(16) float g_wp[1048576];
__device__ __align__(16) float g_enorm[512];
__device__ __align__(16) float g_scale[256];
__device__ __align__(16) float g_part[512];

struct GemmP {
    const float* A; const float* W; const float* bias; const float* res; float* out;
    const float* ascale; const float* aweight;
    int N, K;
    int IC, IH, IW, OH, OW, stride, padh, padw;
    int oscale, ooffh, ooffw, oW, oHW;
    int mode;   // 0 plain, 1 bias+relu, 2 res+bias+relu
};

__device__ __forceinline__ unsigned pack_bf16x2(float lo, float hi) {
    unsigned r;
    asm("cvt.rn.bf16x2.f32 %0, %1, %2;" : "=r"(r) : "f"(hi), "f"(lo));
    return r;
}
__device__ __forceinline__ void mma_bf16(float* d, const unsigned* a, const unsigned* b) {
    asm volatile(
        "mma.sync.aligned.m16n8k16.row.col.f32.bf16.bf16.f32 "
        "{%0,%1,%2,%3}, {%4,%5,%6,%7}, {%8,%9}, {%0,%1,%2,%3};"
        : "+f"(d[0]), "+f"(d[1]), "+f"(d[2]), "+f"(d[3])
        : "r"(a[0]), "r"(a[1]), "r"(a[2]), "r"(a[3]), "r"(b[0]), "r"(b[1]));
}

// smem word layout per buffer: Ah[8*136] Al[8*136] Bh[8*264] Bl[8*264]
#define A2_STR 136
#define B2_STR 264
#define AH_OFF 0
#define AL_OFF (8 * A2_STR)
#define BH_OFF (2 * 8 * A2_STR)
#define BL_OFF (2 * 8 * A2_STR + 8 * B2_STR)
#define BUF_WORDS (2 * 8 * A2_STR + 2 * 8 * B2_STR)   // 6400
#define SMEM_BYTES (2 * BUF_WORDS * 4)                 // 51200

// ---------------------------------------------------------------------------
// bf16x3 conv GEMM: CTA 128(M) x 256(N), K-tile 16, warps 2m x 4n (64x64).
// ---------------------------------------------------------------------------
template<int KH, int KW, bool RMS>
__global__ __launch_bounds__(256, 1) void conv_bf16(GemmP p) {
    constexpr int KHKW = KH * KW;
    extern __shared__ unsigned smem[];
    __shared__ int sY[128], sX[128], sBase[128], sObase[128];
    __shared__ float sScl[128];

    const int tid = threadIdx.x;
    const int bm = blockIdx.x * 128;
    const int bn = blockIdx.y * 256;

    if (tid < 128) {
        int m = bm + tid;
        int ohw = p.OH * p.OW;
        int n = m / ohw;
        int rem = m - n * ohw;
        int oh = rem / p.OW;
        int ow = rem - oh * p.OW;
        sBase[tid] = n * p.IC * p.IH * p.IW;
        sY[tid] = oh * p.stride - p.padh;
        sX[tid] = ow * p.stride - p.padw;
        sObase[tid] = n * p.N * p.oHW + (oh * p.oscale + p.ooffh) * p.oW
                      + (ow * p.oscale + p.ooffw);
        sScl[tid] = RMS ? p.ascale[n] : 1.f;
    }
    __syncthreads();

    const int IH = p.IH, IW = p.IW;
    // A-gather role: row r, 8 consecutive k (pairs kb2..kb2+3)
    const int r = tid & 127;
    const int jset = (tid >> 7) * 8;
    const int kb2 = (tid >> 7) * 4;
    const int rby = sY[r], rbx = sX[r], rbb = sBase[r];
    const float ascl = sScl[r];
    // B role: row nb (=oc 0..255), all 16 k of the tile
    const int nb = tid;
    const float* Wrow = p.W + (size_t)(bn + nb) * p.K;

    // warp roles: 2m x 4n, warp tile 64x64
    const int w = tid >> 5, lane = tid & 31;
    const int wm = (w & 1) * 64, wn = (w >> 1) * 64;
    const int lg = lane >> 2, lk = lane & 3;

    float acc[4][8][4];
#pragma unroll
    for (int i = 0; i < 4; i++)
#pragma unroll
        for (int j = 0; j < 8; j++)
#pragma unroll
            for (int e = 0; e < 4; e++) acc[i][j][e] = 0.f;

    float avf[8];
    float bvf[16];

    auto gather = [&](int k0) {
#pragma unroll
        for (int q = 0; q < 8; q++) {
            int k = k0 + jset + q;
            int ic = k / KHKW;
            int kk2 = k - ic * KHKW;
            int kh = kk2 / KW;
            int kw = kk2 - kh * KW;
            int ih = rby + kh, iw = rbx + kw;
            float v = 0.f;
            if ((unsigned)ih < (unsigned)IH && (unsigned)iw < (unsigned)IW) {
                int ii = (ic * IH + ih) * IW + iw;
                v = p.A[rbb + ii];
                if (RMS) v *= ascl * p.aweight[ii];
            }
            avf[q] = v;
        }
#pragma unroll
        for (int q4 = 0; q4 < 4; q4++) {
            float4 b = *(const float4*)(Wrow + k0 + q4 * 4);
            bvf[q4 * 4 + 0] = b.x; bvf[q4 * 4 + 1] = b.y;
            bvf[q4 * 4 + 2] = b.z; bvf[q4 * 4 + 3] = b.w;
        }
    };
    auto store = [&](int buf) {
        unsigned* base = smem + buf * BUF_WORDS;
#pragma unroll
        for (int c = 0; c < 4; c++) {
            float v0 = avf[2 * c], v1 = avf[2 * c + 1];
            unsigned ph = pack_bf16x2(v0, v1);
            float l0 = v0 - __uint_as_float(ph << 16);
            float l1 = v1 - __uint_as_float(ph & 0xFFFF0000u);
            base[AH_OFF + (kb2 + c) * A2_STR + r] = ph;
            base[AL_OFF + (kb2 + c) * A2_STR + r] = pack_bf16x2(l0, l1);
        }
#pragma unroll
        for (int c = 0; c < 8; c++) {
            float v0 = bvf[2 * c], v1 = bvf[2 * c + 1];
            unsigned ph = pack_bf16x2(v0, v1);
            float l0 = v0 - __uint_as_float(ph << 16);
            float l1 = v1 - __uint_as_float(ph & 0xFFFF0000u);
            base[BH_OFF + c * B2_STR + nb] = ph;
            base[BL_OFF + c * B2_STR + nb] = pack_bf16x2(l0, l1);
        }
    };

    const int ntiles = p.K >> 4;
    gather(0);
    store(0);
    __syncthreads();

    for (int t = 0; t < ntiles; t++) {
        const int cur = t & 1;
        const unsigned* Ah = smem + cur * BUF_WORDS + AH_OFF;
        const unsigned* Al = smem + cur * BUF_WORDS + AL_OFF;
        const unsigned* Bh = smem + cur * BUF_WORDS + BH_OFF;
        const unsigned* Bl = smem + cur * BUF_WORDS + BL_OFF;
        if (t + 1 < ntiles) gather((t + 1) << 4);

        unsigned bfh[8][2], bfl[8][2];
#pragma unroll
        for (int nt = 0; nt < 8; nt++) {
            int nl = wn + nt * 8 + lg;
            bfh[nt][0] = Bh[lk * B2_STR + nl];
            bfh[nt][1] = Bh[(lk + 4) * B2_STR + nl];
            bfl[nt][0] = Bl[lk * B2_STR + nl];
            bfl[nt][1] = Bl[(lk + 4) * B2_STR + nl];
        }
#pragma unroll
        for (int mt = 0; mt < 4; mt++) {
            int ml = wm + mt * 16 + lg;
            unsigned afh[4], afl[4];
            afh[0] = Ah[lk * A2_STR + ml];
            afh[1] = Ah[lk * A2_STR + ml + 8];
            afh[2] = Ah[(lk + 4) * A2_STR + ml];
            afh[3] = Ah[(lk + 4) * A2_STR + ml + 8];
            afl[0] = Al[lk * A2_STR + ml];
            afl[1] = Al[lk * A2_STR + ml + 8];
            afl[2] = Al[(lk + 4) * A2_STR + ml];
            afl[3] = Al[(lk + 4) * A2_STR + ml + 8];
#pragma unroll
            for (int nt = 0; nt < 8; nt++) {
                mma_bf16(acc[mt][nt], afh, bfh[nt]);
                mma_bf16(acc[mt][nt], afl, bfh[nt]);
                mma_bf16(acc[mt][nt], afh, bfl[nt]);
            }
        }
        if (t + 1 < ntiles) {
            store(cur ^ 1);
            __syncthreads();
        }
    }

    const int oHW = p.oHW;
#pragma unroll
    for (int mt = 0; mt < 4; mt++) {
#pragma unroll
        for (int half = 0; half < 2; half++) {
            int ml = wm + mt * 16 + lg + half * 8;
            int obase = sObase[ml];
#pragma unroll
            for (int nt = 0; nt < 8; nt++) {
                int oc = bn + wn + nt * 8 + lk * 2;
                float v0 = acc[mt][nt][half * 2 + 0];
                float v1 = acc[mt][nt][half * 2 + 1];
                if (p.bias) { v0 += p.bias[oc]; v1 += p.bias[oc + 1]; }
                if (p.mode >= 1) { v0 = fmaxf(v0, 0.f); v1 = fmaxf(v1, 0.f); }
                size_t oi0 = (size_t)obase + (size_t)oc * oHW;
                size_t oi1 = oi0 + oHW;
                if (p.mode == 2) { v0 += p.res[oi0]; v1 += p.res[oi1]; }
                p.out[oi0] = v0;
                p.out[oi1] = v1;
            }
        }
    }
}

// ---------------------------------------------------------------------------
// Exact fp32 SIMT GEMM (VQ scores, 1x1). 128x128 tile, 8x8/thread.
// ---------------------------------------------------------------------------
__global__ __launch_bounds__(256) void conv_gemm_simt(GemmP p) {
    __shared__ float As[2][16][128];
    __shared__ float Bs[2][16][128];
    __shared__ int sBase[128];

    const int tid = threadIdx.x;
    const int bm = blockIdx.x * 128;
    const int bn = blockIdx.y * 128;

    if (tid < 128) {
        int m = bm + tid;
        int ohw = p.OH * p.OW;
        int n = m / ohw;
        int rem = m - n * ohw;
        sBase[tid] = n * p.IC * p.IH * p.IW + rem;
    }
    __syncthreads();

    const int r = tid & 127;
    const int jset = (tid >> 7) * 8;
    const int rbb = sBase[r];
    const int nb = tid & 127;
    const int kq = (tid >> 7) * 8;
    const float* Wrow = p.W + (size_t)(bn + nb) * p.K;
    const int HWi = p.IH * p.IW;

    float av[8];
    float4 bv0, bv1;
    auto loadAB = [&](int k0) {
#pragma unroll
        for (int q = 0; q < 8; q++) {
            int ic = k0 + jset + q;
            av[q] = p.A[rbb + ic * HWi];
        }
        bv0 = *(const float4*)(Wrow + k0 + kq);
        bv1 = *(const float4*)(Wrow + k0 + kq + 4);
    };
    auto storeAB = [&](int buf) {
#pragma unroll
        for (int q = 0; q < 8; q++) As[buf][jset + q][r] = av[q];
        Bs[buf][kq + 0][nb] = bv0.x; Bs[buf][kq + 1][nb] = bv0.y;
        Bs[buf][kq + 2][nb] = bv0.z; Bs[buf][kq + 3][nb] = bv0.w;
        Bs[buf][kq + 4][nb] = bv1.x; Bs[buf][kq + 5][nb] = bv1.y;
        Bs[buf][kq + 6][nb] = bv1.z; Bs[buf][kq + 7][nb] = bv1.w;
    };

    const int tr = tid >> 4;
    const int tc = tid & 15;
    float acc[8][8];
#pragma unroll
    for (int i = 0; i < 8; i++)
#pragma unroll
        for (int j = 0; j < 8; j++) acc[i][j] = 0.f;

    const int nt = p.K >> 4;
    loadAB(0);
    storeAB(0);
    __syncthreads();
    for (int t = 0; t < nt; t++) {
        const int cur = t & 1;
        if (t + 1 < nt) loadAB((t + 1) << 4);
#pragma unroll
        for (int kk = 0; kk < 16; kk++) {
            float4 a0 = *(const float4*)&As[cur][kk][tr * 8];
            float4 a1 = *(const float4*)&As[cur][kk][tr * 8 + 4];
            float4 b0 = *(const float4*)&Bs[cur][kk][tc * 8];
            float4 b1 = *(const float4*)&Bs[cur][kk][tc * 8 + 4];
            float a[8] = {a0.x, a0.y, a0.z, a0.w, a1.x, a1.y, a1.z, a1.w};
            float b[8] = {b0.x, b0.y, b0.z, b0.w, b1.x, b1.y, b1.z, b1.w};
#pragma unroll
            for (int i = 0; i < 8; i++)
#pragma unroll
                for (int j = 0; j < 8; j++) acc[i][j] += a[i] * b[j];
        }
        if (t + 1 < nt) {
            storeAB(cur ^ 1);
            __syncthreads();
        }
    }

    const int ohw = p.OH * p.OW;
#pragma unroll
    for (int i = 0; i < 8; i++) {
        int m = bm + tr * 8 + i;
        int n = m / ohw;
        int rem = m - n * ohw;
        size_t obase = (size_t)n * p.N * p.oHW + rem;
#pragma unroll
        for (int j = 0; j < 8; j++) {
            int oc = bn + tc * 8 + j;
            p.out[obase + (size_t)oc * p.oHW] = acc[i][j];
        }
    }
}

// ---------------------------------------------------------------------------
__global__ __launch_bounds__(256) void rms_scale_kernel(const float* __restrict__ in,
                                                        float* __restrict__ scale) {
    const int n = blockIdx.x;
    const float4* xp = (const float4*)(in + (size_t)n * 16384);
    float s = 0.f;
    for (int i = threadIdx.x; i < 4096; i += 256) {
        float4 v = xp[i];
        s += v.x * v.x + v.y * v.y + v.z * v.z + v.w * v.w;
    }
    __shared__ float sh[256];
    sh[threadIdx.x] = s;
    __syncthreads();
    for (int st = 128; st > 0; st >>= 1) {
        if (threadIdx.x < st) sh[threadIdx.x] += sh[threadIdx.x + st];
        __syncthreads();
    }
    if (threadIdx.x == 0)
        scale[n] = rsqrtf(sh[0] * (1.f / 16384.f) + 1.1920929e-07f);
}

__global__ void enorm_kernel(const float* __restrict__ e, float* __restrict__ en) {
    int j = blockIdx.x * 256 + threadIdx.x;
    if (j >= NE) return;
    const float* r = e + (size_t)j * HS;
    float s = 0.f;
    for (int c = 0; c < HS; c++) { float v = r[c]; s += v * v; }
    en[j] = s;
}

__global__ __launch_bounds__(256) void vq_argmin_kernel(const float* __restrict__ scores,
                                                        const float* __restrict__ en,
                                                        const float* __restrict__ emb,
                                                        float* __restrict__ q) {
    int token = blockIdx.x * 8 + (threadIdx.x >> 5);
    int lane = threadIdx.x & 31;
    int n = token >> 6, hw = token & 63;
    const float* sc = scores + ((size_t)n * NE) * 64 + hw;
    float best = 3.4e38f;
    int bj = NE;
    for (int j = lane; j < NE; j += 32) {
        float d = en[j] - 2.f * sc[(size_t)j * 64];
        if (d < best || (d == best && j < bj)) { best = d; bj = j; }
    }
#pragma unroll
    for (int off = 16; off; off >>= 1) {
        float ob = __shfl_down_sync(0xffffffffu, best, off);
        int oj = __shfl_down_sync(0xffffffffu, bj, off);
        if (ob < best || (ob == best && oj < bj)) { best = ob; bj = oj; }
    }
    bj = __shfl_sync(0xffffffffu, bj, 0);
    const float* er = emb + (size_t)bj * HS;
    float* qp = q + (size_t)n * HS * 64 + hw;
    for (int c = lane; c < HS; c += 32) qp[(size_t)c * 64] = er[c];
}

__global__ __launch_bounds__(256) void sqdiff_kernel(const float* __restrict__ a,
                                                     const float* __restrict__ b,
                                                     float* __restrict__ part, int nvec4) {
    const float4* a4 = (const float4*)a;
    const float4* b4 = (const float4*)b;
    float s = 0.f;
    for (int i = blockIdx.x * 256 + threadIdx.x; i < nvec4; i += 256 * 256) {
        float4 va = a4[i], vb = b4[i];
        float dx = va.x - vb.x, dy = va.y - vb.y, dz = va.z - vb.z, dw = va.w - vb.w;
        s += dx * dx + dy * dy + dz * dz + dw * dw;
    }
    __shared__ float sh[256];
    sh[threadIdx.x] = s;
    __syncthreads();
    for (int st = 128; st > 0; st >>= 1) {
        if (threadIdx.x < st) sh[threadIdx.x] += sh[threadIdx.x + st];
        __syncthreads();
    }
    if (threadIdx.x == 0) part[blockIdx.x] = sh[0];
}

__global__ void finalize_kernel(const float* __restrict__ partVq,
                                const float* __restrict__ partRec,
                                float* __restrict__ out) {
    if (threadIdx.x == 0 && blockIdx.x == 0) {
        float svq = 0.f, sre = 0.f;
        for (int i = 0; i < 256; i++) { svq += partVq[i]; sre += partRec[i]; }
        float dict = svq * (1.f / 4194304.f);
        float rec = sre * (1.f / 786432.f);
        out[0] = rec + dict + dict;
        out[1] = rec;
        out[2] = dict;
        out[3] = dict;
    }
}

__global__ void prep_wp_kernel(const float* __restrict__ w, float* __restrict__ wp) {
    int idx = blockIdx.x * 256 + threadIdx.x;
    if (idx >= 1048576) return;
    int b = idx & 1;
    int a = (idx >> 1) & 1;
    int ic = (idx >> 2) & 255;
    int oc = (idx >> 10) & 255;
    int p = idx >> 18;
    int ph = p >> 1, pw = p & 1;
    int kh = ph + 2 * a, kw = pw + 2 * b;
    wp[idx] = w[((size_t)(ic * 256 + oc) * 4 + (3 - kh)) * 4 + (3 - kw)];
}

__global__ __launch_bounds__(256) void deconv2_kernel(const float* __restrict__ in,
                                                      const float* __restrict__ w,
                                                      const float* __restrict__ bias,
                                                      float* __restrict__ out) {
    __shared__ float wsh[4 * 256 * 3];
    const int n = blockIdx.x;
    const int par = blockIdx.y;
    const int ph = par >> 1, pw = par & 1;
    const int tid = threadIdx.x;

    for (int idx = tid; idx < 3072; idx += 256) {
        int oc = idx % 3;
        int rest = idx / 3;
        int ic = rest & 255;
        int t = rest >> 8;
        int a = t >> 1, b = t & 1;
        int kh = ph + 2 * a, kw = pw + 2 * b;
        wsh[idx] = w[((size_t)(ic * 3 + oc) * 4 + (3 - kh)) * 4 + (3 - kw)];
    }
    __syncthreads();

    const int i = tid >> 4, j = tid & 15;
    const int oh = 2 * i + ph, ow = 2 * j + pw;
    float acc0 = 0.f, acc1 = 0.f, acc2 = 0.f;

    int base[4];
    bool ok[4];
#pragma unroll
    for (int t = 0; t < 4; t++) {
        int a = t >> 1, b = t & 1;
        int ih = i + ph + a - 1, iw = j + pw + b - 1;
        ok[t] = ((unsigned)ih < 16u) && ((unsigned)iw < 16u);
        base[t] = ok[t] ? (n * 65536 + ih * 16 + iw) : 0;
    }
    for (int ic = 0; ic < 256; ic++) {
        int ico = ic * 256;
#pragma unroll
        for (int t = 0; t < 4; t++) {
            if (ok[t]) {
                float v = in[base[t] + ico];
                const float* wp2 = &wsh[(t * 256 + ic) * 3];
                acc0 += v * wp2[0];
                acc1 += v * wp2[1];
                acc2 += v * wp2[2];
            }
        }
    }
    size_t o = (size_t)n * 3072 + (size_t)oh * 32 + ow;
    out[o] = acc0 + bias[0];
    out[o + 1024] = acc1 + bias[1];
    out[o + 2048] = acc2 + bias[2];
}

// ---------------------------------------------------------------------------
static GemmP mkP(const float* A, const float* W, const float* bias, const float* res,
                 float* out, const float* ascale, const float* aweight,
                 int N, int K, int IC, int IH, int IW, int OH, int OW,
                 int stride, int padh, int padw,
                 int oscale, int ooffh, int ooffw, int oW, int oHW, int mode) {
    GemmP p;
    p.A = A; p.W = W; p.bias = bias; p.res = res; p.out = out;
    p.ascale = ascale; p.aweight = aweight;
    p.N = N; p.K = K; p.IC = IC; p.IH = IH; p.IW = IW; p.OH = OH; p.OW = OW;
    p.stride = stride; p.padh = padh; p.padw = padw;
    p.oscale = oscale; p.ooffh = ooffh; p.ooffw = ooffw; p.oW = oW; p.oHW = oHW;
    p.mode = mode;
    return p;
}

template<int KH, int KW, bool RMS>
static void launch_bf16(GemmP p, int M) {
    cudaFuncSetAttribute(conv_bf16<KH, KW, RMS>,
                         cudaFuncAttributeMaxDynamicSharedMemorySize, SMEM_BYTES);
    dim3 g(M / 128, p.N / 256);
    conv_bf16<KH, KW, RMS><<<g, 256, SMEM_BYTES>>>(p);
}

static void res_block(float* x, float* tmp, float* scl, const float* rmsw,
                      const float* w3, const float* b3,
                      const float* w1, const float* b1) {
    rms_scale_kernel<<<256, 256>>>(x, scl);
    {
        GemmP p = mkP(x, w3, b3, x, tmp, scl, rmsw,
                      256, 2304, 256, 8, 8, 8, 8, 1, 1, 1,
                      1, 0, 0, 8, 64, 2);
        launch_bf16<3, 3, true>(p, 16384);
    }
    rms_scale_kernel<<<256, 256>>>(tmp, scl);
    {
        GemmP p = mkP(tmp, w1, b1, tmp, x, scl, rmsw + 16384,
                      256, 256, 256, 8, 8, 8, 8, 1, 0, 0,
                      1, 0, 0, 8, 64, 2);
        launch_bf16<1, 1, true>(p, 16384);
    }
}

extern "C" void kernel_launch(void* const* d_in, const int* in_sizes, int n_in,
                              void* d_out, int out_size) {
    const float* x       = (const float*)d_in[0];
    const float* enc_w1  = (const float*)d_in[1];
    const float* enc_b1  = (const float*)d_in[2];
    const float* enc_w2  = (const float*)d_in[3];
    const float* enc_b2  = (const float*)d_in[4];
    const float* rms_w   = (const float*)d_in[5];
    const float* c3_w    = (const float*)d_in[6];
    const float* c3_b    = (const float*)d_in[7];
    const float* c1_w    = (const float*)d_in[8];
    const float* c1_b    = (const float*)d_in[9];
    const float* emb     = (const float*)d_in[10];
    const float* dec_w1  = (const float*)d_in[11];
    const float* dec_b1  = (const float*)d_in[12];
    const float* dec_w2  = (const float*)d_in[13];
    const float* dec_b2  = (const float*)d_in[14];
    float* out = (float*)d_out;

    float *h16, *h8, *t8, *q, *scores, *wp, *en, *scl, *part;
    cudaGetSymbolAddress((void**)&h16, g_h16);
    cudaGetSymbolAddress((void**)&h8, g_h8);
    cudaGetSymbolAddress((void**)&t8, g_t8);
    cudaGetSymbolAddress((void**)&q, g_q);
    cudaGetSymbolAddress((void**)&scores, g_scores);
    cudaGetSymbolAddress((void**)&wp, g_wp);
    cudaGetSymbolAddress((void**)&en, g_enorm);
    cudaGetSymbolAddress((void**)&scl, g_scale);
    cudaGetSymbolAddress((void**)&part, g_part);

    // ---- Encoder ----
    {
        GemmP p = mkP(x, enc_w1, enc_b1, nullptr, h16, nullptr, nullptr,
                      256, 48, 3, 32, 32, 16, 16, 2, 1, 1,
                      1, 0, 0, 16, 256, 1);
        launch_bf16<4, 4, false>(p, 65536);
    }
    {
        GemmP p = mkP(h16, enc_w2, enc_b2, nullptr, h8, nullptr, nullptr,
                      256, 4096, 256, 16, 16, 8, 8, 2, 1, 1,
                      1, 0, 0, 8, 64, 1);
        launch_bf16<4, 4, false>(p, 16384);
    }
    res_block(h8, t8, scl, rms_w + 0 * 32768, c3_w + 0 * 589824, c3_b + 0 * 256,
              c1_w + 0 * 65536, c1_b + 0 * 256);
    res_block(h8, t8, scl, rms_w + 1 * 32768, c3_w + 1 * 589824, c3_b + 1 * 256,
              c1_w + 1 * 65536, c1_b + 1 * 256);

    // ---- VQ (exact fp32 scores) ----
    enorm_kernel<<<2, 256>>>(emb, en);
    {
        GemmP p = mkP(h8, emb, nullptr, nullptr, scores, nullptr, nullptr,
                      512, 256, 256, 8, 8, 8, 8, 1, 0, 0,
                      1, 0, 0, 8, 64, 0);
        conv_gemm_simt<<<dim3(128, 4), 256>>>(p);
    }
    vq_argmin_kernel<<<2048, 256>>>(scores, en, emb, q);
    sqdiff_kernel<<<256, 256>>>(h8, q, part, 1048576);

    // ---- Decoder ----
    res_block(q, t8, scl, rms_w + 2 * 32768, c3_w + 2 * 589824, c3_b + 2 * 256,
              c1_w + 2 * 65536, c1_b + 2 * 256);
    res_block(q, t8, scl, rms_w + 3 * 32768, c3_w + 3 * 589824, c3_b + 3 * 256,
              c1_w + 3 * 65536, c1_b + 3 * 256);

    prep_wp_kernel<<<4096, 256>>>(dec_w1, wp);
    for (int par = 0; par < 4; par++) {
        int ph = par >> 1, pw = par & 1;
        GemmP p = mkP(q, wp + (size_t)par * 262144, dec_b1, nullptr, h16, nullptr, nullptr,
                      256, 1024, 256, 8, 8, 8, 8, 1, 1 - ph, 1 - pw,
                      2, ph, pw, 16, 256, 1);
        launch_bf16<2, 2, false>(p, 16384);
    }

    deconv2_kernel<<<dim3(256, 4), 256>>>(h16, dec_w2, dec_b2, out + 4);

    sqdiff_kernel<<<256, 256>>>(out + 4, x, part + 256, 196608);
    finalize_kernel<<<1, 32>>>(part, part + 256, out);
}

// round 10
// speedup vs baseline: 1.4709x; 1.0174x over previous
#include <cuda_runtime.h>
#include <cstddef>
#include <cstdint>

// ---------------------------------------------------------------------------
// VQ-VAE forward. All GEMMs (convs + VQ scores) via bf16x3 emulated-fp32
// mma.sync.m16n8k16 (a=ah+al, b=bh+bl bf16; acc += ah*bh+al*bh+ah*bl).
// CTA tile 128x128, 8 warps 2m x 4n -> 64x32 warp tile, K-tile 16,
// double-buffered packed smem, 2 CTAs/SM. Deconv1 parities fused via grid.z.
// Scratch in __device__ globals. Graph-capturable.
// ---------------------------------------------------------------------------

#define HS 256
#define NE 512

__device__ __align__(16) float g_h16[16777216];
__device__ __align__(16) float g_h8[4194304];
__device__ __align__(16) float g_t8[4194304];
__device__ __align__(16) float g_q[4194304];
__device__ __align__(16) float g_scores[8388608];
__device__ __align__(16) float g_wp[1048576];
__device__ __align__(16) float g_enorm[512];
__device__ __align__(16) float g_scale[256];
__device__ __align__(16) float g_part[512];

struct GemmP {
    const float* A; const float* W; const float* bias; const float* res; float* out;
    const float* ascale; const float* aweight;
    int N, K;
    int IC, IH, IW, OH, OW, stride, padh, padw;
    int oscale, ooffh, ooffw, oW, oHW;
    int mode;   // 0 plain, 1 bias+relu, 2 res+bias+relu
};

__device__ __forceinline__ unsigned pack_bf16x2(float lo, float hi) {
    unsigned r;
    asm("cvt.rn.bf16x2.f32 %0, %1, %2;" : "=r"(r) : "f"(hi), "f"(lo));
    return r;
}
__device__ __forceinline__ void mma_bf16(float* d, const unsigned* a, const unsigned* b) {
    asm volatile(
        "mma.sync.aligned.m16n8k16.row.col.f32.bf16.bf16.f32 "
        "{%0,%1,%2,%3}, {%4,%5,%6,%7}, {%8,%9}, {%0,%1,%2,%3};"
        : "+f"(d[0]), "+f"(d[1]), "+f"(d[2]), "+f"(d[3])
        : "r"(a[0]), "r"(a[1]), "r"(a[2]), "r"(a[3]), "r"(b[0]), "r"(b[1]));
}

// smem: per buffer Ah[8*136] Al[8*136] Bh[8*136] Bl[8*136] (packed bf16x2 words)
#define STR2 136
#define AH_OFF 0
#define AL_OFF (8 * STR2)
#define BH_OFF (16 * STR2)
#define BL_OFF (24 * STR2)
#define BUF_WORDS (32 * STR2)   // 4352

// ---------------------------------------------------------------------------
// bf16x3 conv GEMM: CTA 128(M) x 128(N), K-tile 16, warps 2m x 4n (64x32).
// PAR4: deconv1 parity fusion via blockIdx.z (overrides pad/off/W).
// ---------------------------------------------------------------------------
template<int KH, int KW, bool RMS, bool PAR4>
__global__ __launch_bounds__(256, 2) void conv_bf16(GemmP p) {
    constexpr int KHKW = KH * KW;
    __shared__ unsigned smem[2 * BUF_WORDS];
    __shared__ int sY[128], sX[128], sBase[128], sObase[128];
    __shared__ float sScl[128];

    const int tid = threadIdx.x;
    const int bm = blockIdx.x * 128;
    const int bn = blockIdx.y * 128;

    int padh = p.padh, padw = p.padw, ooffh = p.ooffh, ooffw = p.ooffw;
    const float* Wbase = p.W;
    if (PAR4) {
        int z = blockIdx.z;
        int ph = z >> 1, pw = z & 1;
        padh = 1 - ph; padw = 1 - pw;
        ooffh = ph; ooffw = pw;
        Wbase += (size_t)z * 262144;
    }

    if (tid < 128) {
        int m = bm + tid;
        int ohw = p.OH * p.OW;
        int n = m / ohw;
        int rem = m - n * ohw;
        int oh = rem / p.OW;
        int ow = rem - oh * p.OW;
        sBase[tid] = n * p.IC * p.IH * p.IW;
        sY[tid] = oh * p.stride - padh;
        sX[tid] = ow * p.stride - padw;
        sObase[tid] = n * p.N * p.oHW + (oh * p.oscale + ooffh) * p.oW
                      + (ow * p.oscale + ooffw);
        sScl[tid] = RMS ? p.ascale[n] : 1.f;
    }
    __syncthreads();

    const int IH = p.IH, IW = p.IW;
    // A-gather: row r (0..127), 8 consecutive k
    const int r = tid & 127;
    const int jset = (tid >> 7) * 8;
    const int kb2 = (tid >> 7) * 4;
    const int rby = sY[r], rbx = sX[r], rbb = sBase[r];
    const float ascl = sScl[r];
    // B-gather: row nb (0..127), 8 consecutive k
    const float* Wrow = Wbase + (size_t)(bn + r) * p.K;

    // warps 2m x 4n -> 64x32 tile
    const int w = tid >> 5, lane = tid & 31;
    const int wm = (w & 1) * 64, wn = (w >> 1) * 32;
    const int lg = lane >> 2, lk = lane & 3;

    float acc[4][4][4];
#pragma unroll
    for (int i = 0; i < 4; i++)
#pragma unroll
        for (int j = 0; j < 4; j++)
#pragma unroll
            for (int e = 0; e < 4; e++) acc[i][j][e] = 0.f;

    float avf[8], bvf[8];

    auto gather = [&](int k0) {
#pragma unroll
        for (int q = 0; q < 8; q++) {
            int k = k0 + jset + q;
            int ic = k / KHKW;
            int kk2 = k - ic * KHKW;
            int kh = kk2 / KW;
            int kw = kk2 - kh * KW;
            int ih = rby + kh, iw = rbx + kw;
            float v = 0.f;
            if ((unsigned)ih < (unsigned)IH && (unsigned)iw < (unsigned)IW) {
                int ii = (ic * IH + ih) * IW + iw;
                v = p.A[rbb + ii];
                if (RMS) v *= ascl * p.aweight[ii];
            }
            avf[q] = v;
        }
#pragma unroll
        for (int q4 = 0; q4 < 2; q4++) {
            float4 b = *(const float4*)(Wrow + k0 + jset + q4 * 4);
            bvf[q4 * 4 + 0] = b.x; bvf[q4 * 4 + 1] = b.y;
            bvf[q4 * 4 + 2] = b.z; bvf[q4 * 4 + 3] = b.w;
        }
    };
    auto store = [&](int buf) {
        unsigned* base = smem + buf * BUF_WORDS;
#pragma unroll
        for (int c = 0; c < 4; c++) {
            float v0 = avf[2 * c], v1 = avf[2 * c + 1];
            unsigned ph = pack_bf16x2(v0, v1);
            float l0 = v0 - __uint_as_float(ph << 16);
            float l1 = v1 - __uint_as_float(ph & 0xFFFF0000u);
            base[AH_OFF + (kb2 + c) * STR2 + r] = ph;
            base[AL_OFF + (kb2 + c) * STR2 + r] = pack_bf16x2(l0, l1);
        }
#pragma unroll
        for (int c = 0; c < 4; c++) {
            float v0 = bvf[2 * c], v1 = bvf[2 * c + 1];
            unsigned ph = pack_bf16x2(v0, v1);
            float l0 = v0 - __uint_as_float(ph << 16);
            float l1 = v1 - __uint_as_float(ph & 0xFFFF0000u);
            base[BH_OFF + (kb2 + c) * STR2 + r] = ph;
            base[BL_OFF + (kb2 + c) * STR2 + r] = pack_bf16x2(l0, l1);
        }
    };

    const int ntiles = p.K >> 4;
    gather(0);
    store(0);
    __syncthreads();

    for (int t = 0; t < ntiles; t++) {
        const int cur = t & 1;
        const unsigned* Ah = smem + cur * BUF_WORDS + AH_OFF;
        const unsigned* Al = smem + cur * BUF_WORDS + AL_OFF;
        const unsigned* Bh = smem + cur * BUF_WORDS + BH_OFF;
        const unsigned* Bl = smem + cur * BUF_WORDS + BL_OFF;
        if (t + 1 < ntiles) gather((t + 1) << 4);

        unsigned bfh[4][2], bfl[4][2];
#pragma unroll
        for (int nt = 0; nt < 4; nt++) {
            int nl = wn + nt * 8 + lg;
            bfh[nt][0] = Bh[lk * STR2 + nl];
            bfh[nt][1] = Bh[(lk + 4) * STR2 + nl];
            bfl[nt][0] = Bl[lk * STR2 + nl];
            bfl[nt][1] = Bl[(lk + 4) * STR2 + nl];
        }
#pragma unroll
        for (int mt = 0; mt < 4; mt++) {
            int ml = wm + mt * 16 + lg;
            unsigned afh[4], afl[4];
            afh[0] = Ah[lk * STR2 + ml];
            afh[1] = Ah[lk * STR2 + ml + 8];
            afh[2] = Ah[(lk + 4) * STR2 + ml];
            afh[3] = Ah[(lk + 4) * STR2 + ml + 8];
            afl[0] = Al[lk * STR2 + ml];
            afl[1] = Al[lk * STR2 + ml + 8];
            afl[2] = Al[(lk + 4) * STR2 + ml];
            afl[3] = Al[(lk + 4) * STR2 + ml + 8];
#pragma unroll
            for (int nt = 0; nt < 4; nt++) {
                mma_bf16(acc[mt][nt], afh, bfh[nt]);
                mma_bf16(acc[mt][nt], afl, bfh[nt]);
                mma_bf16(acc[mt][nt], afh, bfl[nt]);
            }
        }
        if (t + 1 < ntiles) {
            store(cur ^ 1);
            __syncthreads();
        }
    }

    const int oHW = p.oHW;
#pragma unroll
    for (int mt = 0; mt < 4; mt++) {
#pragma unroll
        for (int half = 0; half < 2; half++) {
            int ml = wm + mt * 16 + lg + half * 8;
            int obase = sObase[ml];
#pragma unroll
            for (int nt = 0; nt < 4; nt++) {
                int oc = bn + wn + nt * 8 + lk * 2;
                float v0 = acc[mt][nt][half * 2 + 0];
                float v1 = acc[mt][nt][half * 2 + 1];
                if (p.bias) { v0 += p.bias[oc]; v1 += p.bias[oc + 1]; }
                if (p.mode >= 1) { v0 = fmaxf(v0, 0.f); v1 = fmaxf(v1, 0.f); }
                size_t oi0 = (size_t)obase + (size_t)oc * oHW;
                size_t oi1 = oi0 + oHW;
                if (p.mode == 2) { v0 += p.res[oi0]; v1 += p.res[oi1]; }
                p.out[oi0] = v0;
                p.out[oi1] = v1;
            }
        }
    }
}

// ---------------------------------------------------------------------------
__global__ __launch_bounds__(256) void rms_scale_kernel(const float* __restrict__ in,
                                                        float* __restrict__ scale) {
    const int n = blockIdx.x;
    const float4* xp = (const float4*)(in + (size_t)n * 16384);
    float s = 0.f;
    for (int i = threadIdx.x; i < 4096; i += 256) {
        float4 v = xp[i];
        s += v.x * v.x + v.y * v.y + v.z * v.z + v.w * v.w;
    }
    __shared__ float sh[256];
    sh[threadIdx.x] = s;
    __syncthreads();
    for (int st = 128; st > 0; st >>= 1) {
        if (threadIdx.x < st) sh[threadIdx.x] += sh[threadIdx.x + st];
        __syncthreads();
    }
    if (threadIdx.x == 0)
        scale[n] = rsqrtf(sh[0] * (1.f / 16384.f) + 1.1920929e-07f);
}

__global__ void enorm_kernel(const float* __restrict__ e, float* __restrict__ en) {
    int j = blockIdx.x * 256 + threadIdx.x;
    if (j >= NE) return;
    const float* r = e + (size_t)j * HS;
    float s = 0.f;
    for (int c = 0; c < HS; c++) { float v = r[c]; s += v * v; }
    en[j] = s;
}

__global__ __launch_bounds__(256) void vq_argmin_kernel(const float* __restrict__ scores,
                                                        const float* __restrict__ en,
                                                        const float* __restrict__ emb,
                                                        float* __restrict__ q) {
    int token = blockIdx.x * 8 + (threadIdx.x >> 5);
    int lane = threadIdx.x & 31;
    int n = token >> 6, hw = token & 63;
    const float* sc = scores + ((size_t)n * NE) * 64 + hw;
    float best = 3.4e38f;
    int bj = NE;
    for (int j = lane; j < NE; j += 32) {
        float d = en[j] - 2.f * sc[(size_t)j * 64];
        if (d < best || (d == best && j < bj)) { best = d; bj = j; }
    }
#pragma unroll
    for (int off = 16; off; off >>= 1) {
        float ob = __shfl_down_sync(0xffffffffu, best, off);
        int oj = __shfl_down_sync(0xffffffffu, bj, off);
        if (ob < best || (ob == best && oj < bj)) { best = ob; bj = oj; }
    }
    bj = __shfl_sync(0xffffffffu, bj, 0);
    const float* er = emb + (size_t)bj * HS;
    float* qp = q + (size_t)n * HS * 64 + hw;
    for (int c = lane; c < HS; c += 32) qp[(size_t)c * 64] = er[c];
}

__global__ __launch_bounds__(256) void sqdiff_kernel(const float* __restrict__ a,
                                                     const float* __restrict__ b,
                                                     float* __restrict__ part, int nvec4) {
    const float4* a4 = (const float4*)a;
    const float4* b4 = (const float4*)b;
    float s = 0.f;
    for (int i = blockIdx.x * 256 + threadIdx.x; i < nvec4; i += 256 * 256) {
        float4 va = a4[i], vb = b4[i];
        float dx = va.x - vb.x, dy = va.y - vb.y, dz = va.z - vb.z, dw = va.w - vb.w;
        s += dx * dx + dy * dy + dz * dz + dw * dw;
    }
    __shared__ float sh[256];
    sh[threadIdx.x] = s;
    __syncthreads();
    for (int st = 128; st > 0; st >>= 1) {
        if (threadIdx.x < st) sh[threadIdx.x] += sh[threadIdx.x + st];
        __syncthreads();
    }
    if (threadIdx.x == 0) part[blockIdx.x] = sh[0];
}

__global__ void finalize_kernel(const float* __restrict__ partVq,
                                const float* __restrict__ partRec,
                                float* __restrict__ out) {
    if (threadIdx.x == 0 && blockIdx.x == 0) {
        float svq = 0.f, sre = 0.f;
        for (int i = 0; i < 256; i++) { svq += partVq[i]; sre += partRec[i]; }
        float dict = svq * (1.f / 4194304.f);
        float rec = sre * (1.f / 786432.f);
        out[0] = rec + dict + dict;
        out[1] = rec;
        out[2] = dict;
        out[3] = dict;
    }
}

__global__ void prep_wp_kernel(const float* __restrict__ w, float* __restrict__ wp) {
    int idx = blockIdx.x * 256 + threadIdx.x;
    if (idx >= 1048576) return;
    int b = idx & 1;
    int a = (idx >> 1) & 1;
    int ic = (idx >> 2) & 255;
    int oc = (idx >> 10) & 255;
    int p = idx >> 18;
    int ph = p >> 1, pw = p & 1;
    int kh = ph + 2 * a, kw = pw + 2 * b;
    wp[idx] = w[((size_t)(ic * 256 + oc) * 4 + (3 - kh)) * 4 + (3 - kw)];
}

__global__ __launch_bounds__(256) void deconv2_kernel(const float* __restrict__ in,
                                                      const float* __restrict__ w,
                                                      const float* __restrict__ bias,
                                                      float* __restrict__ out) {
    __shared__ float wsh[4 * 256 * 3];
    const int n = blockIdx.x;
    const int par = blockIdx.y;
    const int ph = par >> 1, pw = par & 1;
    const int tid = threadIdx.x;

    for (int idx = tid; idx < 3072; idx += 256) {
        int oc = idx % 3;
        int rest = idx / 3;
        int ic = rest & 255;
        int t = rest >> 8;
        int a = t >> 1, b = t & 1;
        int kh = ph + 2 * a, kw = pw + 2 * b;
        wsh[idx] = w[((size_t)(ic * 3 + oc) * 4 + (3 - kh)) * 4 + (3 - kw)];
    }
    __syncthreads();

    const int i = tid >> 4, j = tid & 15;
    const int oh = 2 * i + ph, ow = 2 * j + pw;
    float acc0 = 0.f, acc1 = 0.f, acc2 = 0.f;

    int base[4];
    bool ok[4];
#pragma unroll
    for (int t = 0; t < 4; t++) {
        int a = t >> 1, b = t & 1;
        int ih = i + ph + a - 1, iw = j + pw + b - 1;
        ok[t] = ((unsigned)ih < 16u) && ((unsigned)iw < 16u);
        base[t] = ok[t] ? (n * 65536 + ih * 16 + iw) : 0;
    }
    for (int ic = 0; ic < 256; ic++) {
        int ico = ic * 256;
#pragma unroll
        for (int t = 0; t < 4; t++) {
            if (ok[t]) {
                float v = in[base[t] + ico];
                const float* wp2 = &wsh[(t * 256 + ic) * 3];
                acc0 += v * wp2[0];
                acc1 += v * wp2[1];
                acc2 += v * wp2[2];
            }
        }
    }
    size_t o = (size_t)n * 3072 + (size_t)oh * 32 + ow;
    out[o] = acc0 + bias[0];
    out[o + 1024] = acc1 + bias[1];
    out[o + 2048] = acc2 + bias[2];
}

// ---------------------------------------------------------------------------
static GemmP mkP(const float* A, const float* W, const float* bias, const float* res,
                 float* out, const float* ascale, const float* aweight,
                 int N, int K, int IC, int IH, int IW, int OH, int OW,
                 int stride, int padh, int padw,
                 int oscale, int ooffh, int ooffw, int oW, int oHW, int mode) {
    GemmP p;
    p.A = A; p.W = W; p.bias = bias; p.res = res; p.out = out;
    p.ascale = ascale; p.aweight = aweight;
    p.N = N; p.K = K; p.IC = IC; p.IH = IH; p.IW = IW; p.OH = OH; p.OW = OW;
    p.stride = stride; p.padh = padh; p.padw = padw;
    p.oscale = oscale; p.ooffh = ooffh; p.ooffw = ooffw; p.oW = oW; p.oHW = oHW;
    p.mode = mode;
    return p;
}

template<int KH, int KW, bool RMS>
static void launch_bf16(GemmP p, int M) {
    dim3 g(M / 128, p.N / 128);
    conv_bf16<KH, KW, RMS, false><<<g, 256>>>(p);
}

static void res_block(float* x, float* tmp, float* scl, const float* rmsw,
                      const float* w3, const float* b3,
                      const float* w1, const float* b1) {
    rms_scale_kernel<<<256, 256>>>(x, scl);
    {
        GemmP p = mkP(x, w3, b3, x, tmp, scl, rmsw,
                      256, 2304, 256, 8, 8, 8, 8, 1, 1, 1,
                      1, 0, 0, 8, 64, 2);
        launch_bf16<3, 3, true>(p, 16384);
    }
    rms_scale_kernel<<<256, 256>>>(tmp, scl);
    {
        GemmP p = mkP(tmp, w1, b1, tmp, x, scl, rmsw + 16384,
                      256, 256, 256, 8, 8, 8, 8, 1, 0, 0,
                      1, 0, 0, 8, 64, 2);
        launch_bf16<1, 1, true>(p, 16384);
    }
}

extern "C" void kernel_launch(void* const* d_in, const int* in_sizes, int n_in,
                              void* d_out, int out_size) {
    const float* x       = (const float*)d_in[0];
    const float* enc_w1  = (const float*)d_in[1];
    const float* enc_b1  = (const float*)d_in[2];
    const float* enc_w2  = (const float*)d_in[3];
    const float* enc_b2  = (const float*)d_in[4];
    const float* rms_w   = (const float*)d_in[5];
    const float* c3_w    = (const float*)d_in[6];
    const float* c3_b    = (const float*)d_in[7];
    const float* c1_w    = (const float*)d_in[8];
    const float* c1_b    = (const float*)d_in[9];
    const float* emb     = (const float*)d_in[10];
    const float* dec_w1  = (const float*)d_in[11];
    const float* dec_b1  = (const float*)d_in[12];
    const float* dec_w2  = (const float*)d_in[13];
    const float* dec_b2  = (const float*)d_in[14];
    float* out = (float*)d_out;

    float *h16, *h8, *t8, *q, *scores, *wp, *en, *scl, *part;
    cudaGetSymbolAddress((void**)&h16, g_h16);
    cudaGetSymbolAddress((void**)&h8, g_h8);
    cudaGetSymbolAddress((void**)&t8, g_t8);
    cudaGetSymbolAddress((void**)&q, g_q);
    cudaGetSymbolAddress((void**)&scores, g_scores);
    cudaGetSymbolAddress((void**)&wp, g_wp);
    cudaGetSymbolAddress((void**)&en, g_enorm);
    cudaGetSymbolAddress((void**)&scl, g_scale);
    cudaGetSymbolAddress((void**)&part, g_part);

    // ---- Encoder ----
    {
        GemmP p = mkP(x, enc_w1, enc_b1, nullptr, h16, nullptr, nullptr,
                      256, 48, 3, 32, 32, 16, 16, 2, 1, 1,
                      1, 0, 0, 16, 256, 1);
        launch_bf16<4, 4, false>(p, 65536);
    }
    {
        GemmP p = mkP(h16, enc_w2, enc_b2, nullptr, h8, nullptr, nullptr,
                      256, 4096, 256, 16, 16, 8, 8, 2, 1, 1,
                      1, 0, 0, 8, 64, 1);
        launch_bf16<4, 4, false>(p, 16384);
    }
    res_block(h8, t8, scl, rms_w + 0 * 32768, c3_w + 0 * 589824, c3_b + 0 * 256,
              c1_w + 0 * 65536, c1_b + 0 * 256);
    res_block(h8, t8, scl, rms_w + 1 * 32768, c3_w + 1 * 589824, c3_b + 1 * 256,
              c1_w + 1 * 65536, c1_b + 1 * 256);

    // ---- VQ (scores via bf16x3 GEMM; argmin + q gather exact) ----
    enorm_kernel<<<2, 256>>>(emb, en);
    {
        GemmP p = mkP(h8, emb, nullptr, nullptr, scores, nullptr, nullptr,
                      512, 256, 256, 8, 8, 8, 8, 1, 0, 0,
                      1, 0, 0, 8, 64, 0);
        launch_bf16<1, 1, false>(p, 16384);
    }
    vq_argmin_kernel<<<2048, 256>>>(scores, en, emb, q);
    sqdiff_kernel<<<256, 256>>>(h8, q, part, 1048576);

    // ---- Decoder ----
    res_block(q, t8, scl, rms_w + 2 * 32768, c3_w + 2 * 589824, c3_b + 2 * 256,
              c1_w + 2 * 65536, c1_b + 2 * 256);
    res_block(q, t8, scl, rms_w + 3 * 32768, c3_w + 3 * 589824, c3_b + 3 * 256,
              c1_w + 3 * 65536, c1_b + 3 * 256);

    // deconv1: 4 parity GEMMs fused into one launch via grid.z
    prep_wp_kernel<<<4096, 256>>>(dec_w1, wp);
    {
        GemmP p = mkP(q, wp, dec_b1, nullptr, h16, nullptr, nullptr,
                      256, 1024, 256, 8, 8, 8, 8, 1, 0, 0,
                      2, 0, 0, 16, 256, 1);
        conv_bf16<2, 2, false, true><<<dim3(128, 2, 4), 256>>>(p);
    }

    deconv2_kernel<<<dim3(256, 4), 256>>>(h16, dec_w2, dec_b2, out + 4);

    sqdiff_kernel<<<256, 256>>>(out + 4, x, part + 256, 196608);
    finalize_kernel<<<1, 32>>>(part, part + 256, out);
}

// round 12
// speedup vs baseline: 1.6882x; 1.1477x over previous
#include <cuda_runtime.h>
#include <cstddef>
#include <cstdint>

// ---------------------------------------------------------------------------
// VQ-VAE forward. All GEMMs via bf16x3 emulated-fp32 mma.sync.m16n8k16.
// Smem tiles row-major [row][k] with 80B row stride (conflict-free 5-unit
// swizzle); fragments loaded via ldmatrix.m8n8.x4 (12 LDSM vs 48 LDS.32 per
// warp-tile). CTA 128x128, warps 2m x 4n (64x32), K-tile 16, double-buffered,
// 2 CTAs/SM. Deconv1 parities fused via grid.z. Scratch in __device__ globals.
// ---------------------------------------------------------------------------

#define HS 256
#define NE 512

__device__ __align__(16) float g_h16[16777216];
__device__ __align__(16) float g_h8[4194304];
__device__ __align__(16) float g_t8[4194304];
__device__ __align__(16) float g_q[4194304];
__device__ __align__(16) float g_scores[8388608];
__device__ __align__(16) float g_wp[1048576];
__device__ __align__(16) float g_enorm[512];
__device__ __align__(16) float g_scale[256];
__device__ __align__(16) float g_part[512];

struct GemmP {
    const float* A; const float* W; const float* bias; const float* res; float* out;
    const float* ascale; const float* aweight;
    int N, K;
    int IC, IH, IW, OH, OW, stride, padh, padw;
    int oscale, ooffh, ooffw, oW, oHW;
    int mode;   // 0 plain, 1 bias+relu, 2 res+bias+relu
};

__device__ __forceinline__ unsigned pack_bf16x2(float lo, float hi) {
    unsigned r;
    asm("cvt.rn.bf16x2.f32 %0, %1, %2;" : "=r"(r) : "f"(hi), "f"(lo));
    return r;
}
__device__ __forceinline__ void mma_bf16(float* d, const unsigned* a, const unsigned* b) {
    asm volatile(
        "mma.sync.aligned.m16n8k16.row.col.f32.bf16.bf16.f32 "
        "{%0,%1,%2,%3}, {%4,%5,%6,%7}, {%8,%9}, {%0,%1,%2,%3};"
        : "+f"(d[0]), "+f"(d[1]), "+f"(d[2]), "+f"(d[3])
        : "r"(a[0]), "r"(a[1]), "r"(a[2]), "r"(a[3]), "r"(b[0]), "r"(b[1]));
}
__device__ __forceinline__ uint32_t smem_u32(const void* p) {
    uint32_t a;
    asm("{ .reg .u64 t; cvta.to.shared.u64 t, %1; cvt.u32.u64 %0, t; }" : "=r"(a) : "l"(p));
    return a;
}
__device__ __forceinline__ void ldsm4(unsigned* r, uint32_t addr) {
    asm volatile("ldmatrix.sync.aligned.m8n8.x4.shared.b16 {%0,%1,%2,%3}, [%4];"
                 : "=r"(r[0]), "=r"(r[1]), "=r"(r[2]), "=r"(r[3]) : "r"(addr));
}

// Row layout: 80B/row. [0,16)=high k0-7, [16,32)=high k8-15, [32,48)=low k0-7,
// [48,64)=low k8-15, [64,80) pad. A tile 128 rows @ +0; B tile 128 rows @ +10240.
#define ROWB 80
#define TILEB 10240          // 128 * 80
#define BUFB 20480           // A + B

// ---------------------------------------------------------------------------
// bf16x3 conv GEMM: CTA 128(M) x 128(N), K-tile 16, warps 2m x 4n (64x32).
// PAR4: deconv1 parity fusion via blockIdx.z.
// ---------------------------------------------------------------------------
template<int KH, int KW, bool RMS, bool PAR4>
__global__ __launch_bounds__(256, 2) void conv_bf16(GemmP p) {
    constexpr int KHKW = KH * KW;
    __shared__ __align__(16) char smem[2 * BUFB];
    __shared__ int sY[128], sX[128], sBase[128], sObase[128];
    __shared__ float sScl[128];

    const int tid = threadIdx.x;
    const int bm = blockIdx.x * 128;
    const int bn = blockIdx.y * 128;

    int padh = p.padh, padw = p.padw, ooffh = p.ooffh, ooffw = p.ooffw;
    const float* Wbase = p.W;
    if (PAR4) {
        int z = blockIdx.z;
        int ph = z >> 1, pw = z & 1;
        padh = 1 - ph; padw = 1 - pw;
        ooffh = ph; ooffw = pw;
        Wbase += (size_t)z * 262144;
    }

    if (tid < 128) {
        int m = bm + tid;
        int ohw = p.OH * p.OW;
        int n = m / ohw;
        int rem = m - n * ohw;
        int oh = rem / p.OW;
        int ow = rem - oh * p.OW;
        sBase[tid] = n * p.IC * p.IH * p.IW;
        sY[tid] = oh * p.stride - padh;
        sX[tid] = ow * p.stride - padw;
        sObase[tid] = n * p.N * p.oHW + (oh * p.oscale + ooffh) * p.oW
                      + (ow * p.oscale + ooffw);
        sScl[tid] = RMS ? p.ascale[n] : 1.f;
    }
    __syncthreads();

    const int IH = p.IH, IW = p.IW;
    // gather roles: row r (0..127), half selects k0-7 / k8-15
    const int r = tid & 127;
    const int half = tid >> 7;
    const int jset = half * 8;
    const int rby = sY[r], rbx = sX[r], rbb = sBase[r];
    const float ascl = sScl[r];
    const float* Wrow = Wbase + (size_t)(bn + r) * p.K;

    // warps 2m x 4n -> 64x32 tile
    const int w = tid >> 5, lane = tid & 31;
    const int wm = (w & 1) * 64, wn = (w >> 1) * 32;
    const int lg = lane >> 2, lk = lane & 3;

    const uint32_t sb = smem_u32(smem);
    // per-lane ldmatrix address components
    const uint32_t aoff = (uint32_t)((lane & 15) * ROWB + (lane >> 4) * 16);
    const uint32_t boff = (uint32_t)(((lane & 7) + ((lane >> 4) << 3)) * ROWB
                                     + (lane & 8) * 2);

    float acc[4][4][4];
#pragma unroll
    for (int i = 0; i < 4; i++)
#pragma unroll
        for (int j = 0; j < 4; j++)
#pragma unroll
            for (int e = 0; e < 4; e++) acc[i][j][e] = 0.f;

    float avf[8], bvf[8];

    auto gather = [&](int k0) {
#pragma unroll
        for (int q = 0; q < 8; q++) {
            int k = k0 + jset + q;
            int ic = k / KHKW;
            int kk2 = k - ic * KHKW;
            int kh = kk2 / KW;
            int kw = kk2 - kh * KW;
            int ih = rby + kh, iw = rbx + kw;
            float v = 0.f;
            if ((unsigned)ih < (unsigned)IH && (unsigned)iw < (unsigned)IW) {
                int ii = (ic * IH + ih) * IW + iw;
                v = p.A[rbb + ii];
                if (RMS) v *= ascl * p.aweight[ii];
            }
            avf[q] = v;
        }
#pragma unroll
        for (int q4 = 0; q4 < 2; q4++) {
            float4 b = *(const float4*)(Wrow + k0 + jset + q4 * 4);
            bvf[q4 * 4 + 0] = b.x; bvf[q4 * 4 + 1] = b.y;
            bvf[q4 * 4 + 2] = b.z; bvf[q4 * 4 + 3] = b.w;
        }
    };
    auto store = [&](int buf) {
        char* base = smem + buf * BUFB;
        uint4 hv, lv;
        unsigned* hp = (unsigned*)&hv;
        unsigned* lp = (unsigned*)&lv;
#pragma unroll
        for (int c = 0; c < 4; c++) {
            float v0 = avf[2 * c], v1 = avf[2 * c + 1];
            unsigned ph = pack_bf16x2(v0, v1);
            hp[c] = ph;
            lp[c] = pack_bf16x2(v0 - __uint_as_float(ph << 16),
                                v1 - __uint_as_float(ph & 0xFFFF0000u));
        }
        *(uint4*)(base + r * ROWB + half * 16) = hv;
        *(uint4*)(base + r * ROWB + 32 + half * 16) = lv;
#pragma unroll
        for (int c = 0; c < 4; c++) {
            float v0 = bvf[2 * c], v1 = bvf[2 * c + 1];
            unsigned ph = pack_bf16x2(v0, v1);
            hp[c] = ph;
            lp[c] = pack_bf16x2(v0 - __uint_as_float(ph << 16),
                                v1 - __uint_as_float(ph & 0xFFFF0000u));
        }
        *(uint4*)(base + TILEB + r * ROWB + half * 16) = hv;
        *(uint4*)(base + TILEB + r * ROWB + 32 + half * 16) = lv;
    };

    const int ntiles = p.K >> 4;
    gather(0);
    store(0);
    __syncthreads();

    for (int t = 0; t < ntiles; t++) {
        const int cur = t & 1;
        const uint32_t aBase = sb + cur * BUFB;
        const uint32_t bBase = aBase + TILEB;
        if (t + 1 < ntiles) gather((t + 1) << 4);

        // B fragments: 2 ldmatrix.x4 pairs cover nt 0..3 (high + low)
        unsigned bh[2][4], bl[2][4];
#pragma unroll
        for (int ntp = 0; ntp < 2; ntp++) {
            uint32_t ba = bBase + (uint32_t)((wn + ntp * 16) * ROWB) + boff;
            ldsm4(bh[ntp], ba);
            ldsm4(bl[ntp], ba + 32);
        }
#pragma unroll
        for (int mt = 0; mt < 4; mt++) {
            uint32_t aa = aBase + (uint32_t)((wm + mt * 16) * ROWB) + aoff;
            unsigned ah[4], al[4];
            ldsm4(ah, aa);
            ldsm4(al, aa + 32);
#pragma unroll
            for (int nt = 0; nt < 4; nt++) {
                const unsigned* bhp = &bh[nt >> 1][(nt & 1) * 2];
                const unsigned* blp = &bl[nt >> 1][(nt & 1) * 2];
                mma_bf16(acc[mt][nt], ah, bhp);
                mma_bf16(acc[mt][nt], al, bhp);
                mma_bf16(acc[mt][nt], ah, blp);
            }
        }
        if (t + 1 < ntiles) {
            store(cur ^ 1);
            __syncthreads();
        }
    }

    const int oHW = p.oHW;
#pragma unroll
    for (int mt = 0; mt < 4; mt++) {
#pragma unroll
        for (int hf = 0; hf < 2; hf++) {
            int ml = wm + mt * 16 + lg + hf * 8;
            int obase = sObase[ml];
#pragma unroll
            for (int nt = 0; nt < 4; nt++) {
                int oc = bn + wn + nt * 8 + lk * 2;
                float v0 = acc[mt][nt][hf * 2 + 0];
                float v1 = acc[mt][nt][hf * 2 + 1];
                if (p.bias) { v0 += p.bias[oc]; v1 += p.bias[oc + 1]; }
                if (p.mode >= 1) { v0 = fmaxf(v0, 0.f); v1 = fmaxf(v1, 0.f); }
                size_t oi0 = (size_t)obase + (size_t)oc * oHW;
                size_t oi1 = oi0 + oHW;
                if (p.mode == 2) { v0 += p.res[oi0]; v1 += p.res[oi1]; }
                p.out[oi0] = v0;
                p.out[oi1] = v1;
            }
        }
    }
}

// ---------------------------------------------------------------------------
__global__ __launch_bounds__(256) void rms_scale_kernel(const float* __restrict__ in,
                                                        float* __restrict__ scale) {
    const int n = blockIdx.x;
    const float4* xp = (const float4*)(in + (size_t)n * 16384);
    float s = 0.f;
    for (int i = threadIdx.x; i < 4096; i += 256) {
        float4 v = xp[i];
        s += v.x * v.x + v.y * v.y + v.z * v.z + v.w * v.w;
    }
    __shared__ float sh[256];
    sh[threadIdx.x] = s;
    __syncthreads();
    for (int st = 128; st > 0; st >>= 1) {
        if (threadIdx.x < st) sh[threadIdx.x] += sh[threadIdx.x + st];
        __syncthreads();
    }
    if (threadIdx.x == 0)
        scale[n] = rsqrtf(sh[0] * (1.f / 16384.f) + 1.1920929e-07f);
}

__global__ void enorm_kernel(const float* __restrict__ e, float* __restrict__ en) {
    int j = blockIdx.x * 256 + threadIdx.x;
    if (j >= NE) return;
    const float* r = e + (size_t)j * HS;
    float s = 0.f;
    for (int c = 0; c < HS; c++) { float v = r[c]; s += v * v; }
    en[j] = s;
}

__global__ __launch_bounds__(256) void vq_argmin_kernel(const float* __restrict__ scores,
                                                        const float* __restrict__ en,
                                                        const float* __restrict__ emb,
                                                        float* __restrict__ q) {
    int token = blockIdx.x * 8 + (threadIdx.x >> 5);
    int lane = threadIdx.x & 31;
    int n = token >> 6, hw = token & 63;
    const float* sc = scores + ((size_t)n * NE) * 64 + hw;
    float best = 3.4e38f;
    int bj = NE;
    for (int j = lane; j < NE; j += 32) {
        float d = en[j] - 2.f * sc[(size_t)j * 64];
        if (d < best || (d == best && j < bj)) { best = d; bj = j; }
    }
#pragma unroll
    for (int off = 16; off; off >>= 1) {
        float ob = __shfl_down_sync(0xffffffffu, best, off);
        int oj = __shfl_down_sync(0xffffffffu, bj, off);
        if (ob < best || (ob == best && oj < bj)) { best = ob; bj = oj; }
    }
    bj = __shfl_sync(0xffffffffu, bj, 0);
    const float* er = emb + (size_t)bj * HS;
    float* qp = q + (size_t)n * HS * 64 + hw;
    for (int c = lane; c < HS; c += 32) qp[(size_t)c * 64] = er[c];
}

__global__ __launch_bounds__(256) void sqdiff_kernel(const float* __restrict__ a,
                                                     const float* __restrict__ b,
                                                     float* __restrict__ part, int nvec4) {
    const float4* a4 = (const float4*)a;
    const float4* b4 = (const float4*)b;
    float s = 0.f;
    for (int i = blockIdx.x * 256 + threadIdx.x; i < nvec4; i += 256 * 256) {
        float4 va = a4[i], vb = b4[i];
        float dx = va.x - vb.x, dy = va.y - vb.y, dz = va.z - vb.z, dw = va.w - vb.w;
        s += dx * dx + dy * dy + dz * dz + dw * dw;
    }
    __shared__ float sh[256];
    sh[threadIdx.x] = s;
    __syncthreads();
    for (int st = 128; st > 0; st >>= 1) {
        if (threadIdx.x < st) sh[threadIdx.x] += sh[threadIdx.x + st];
        __syncthreads();
    }
    if (threadIdx.x == 0) part[blockIdx.x] = sh[0];
}

__global__ void finalize_kernel(const float* __restrict__ partVq,
                                const float* __restrict__ partRec,
                                float* __restrict__ out) {
    if (threadIdx.x == 0 && blockIdx.x == 0) {
        float svq = 0.f, sre = 0.f;
        for (int i = 0; i < 256; i++) { svq += partVq[i]; sre += partRec[i]; }
        float dict = svq * (1.f / 4194304.f);
        float rec = sre * (1.f / 786432.f);
        out[0] = rec + dict + dict;
        out[1] = rec;
        out[2] = dict;
        out[3] = dict;
    }
}

__global__ void prep_wp_kernel(const float* __restrict__ w, float* __restrict__ wp) {
    int idx = blockIdx.x * 256 + threadIdx.x;
    if (idx >= 1048576) return;
    int b = idx & 1;
    int a = (idx >> 1) & 1;
    int ic = (idx >> 2) & 255;
    int oc = (idx >> 10) & 255;
    int p = idx >> 18;
    int ph = p >> 1, pw = p & 1;
    int kh = ph + 2 * a, kw = pw + 2 * b;
    wp[idx] = w[((size_t)(ic * 256 + oc) * 4 + (3 - kh)) * 4 + (3 - kw)];
}

__global__ __launch_bounds__(256) void deconv2_kernel(const float* __restrict__ in,
                                                      const float* __restrict__ w,
                                                      const float* __restrict__ bias,
                                                      float* __restrict__ out) {
    __shared__ float wsh[4 * 256 * 3];
    const int n = blockIdx.x;
    const int par = blockIdx.y;
    const int ph = par >> 1, pw = par & 1;
    const int tid = threadIdx.x;

    for (int idx = tid; idx < 3072; idx += 256) {
        int oc = idx % 3;
        int rest = idx / 3;
        int ic = rest & 255;
        int t = rest >> 8;
        int a = t >> 1, b = t & 1;
        int kh = ph + 2 * a, kw = pw + 2 * b;
        wsh[idx] = w[((size_t)(ic * 3 + oc) * 4 + (3 - kh)) * 4 + (3 - kw)];
    }
    __syncthreads();

    const int i = tid >> 4, j = tid & 15;
    const int oh = 2 * i + ph, ow = 2 * j + pw;
    float acc0 = 0.f, acc1 = 0.f, acc2 = 0.f;

    int base[4];
    bool ok[4];
#pragma unroll
    for (int t = 0; t < 4; t++) {
        int a = t >> 1, b = t & 1;
        int ih = i + ph + a - 1, iw = j + pw + b - 1;
        ok[t] = ((unsigned)ih < 16u) && ((unsigned)iw < 16u);
        base[t] = ok[t] ? (n * 65536 + ih * 16 + iw) : 0;
    }
    for (int ic = 0; ic < 256; ic++) {
        int ico = ic * 256;
#pragma unroll
        for (int t = 0; t < 4; t++) {
            if (ok[t]) {
                float v = in[base[t] + ico];
                const float* wp2 = &wsh[(t * 256 + ic) * 3];
                acc0 += v * wp2[0];
                acc1 += v * wp2[1];
                acc2 += v * wp2[2];
            }
        }
    }
    size_t o = (size_t)n * 3072 + (size_t)oh * 32 + ow;
    out[o] = acc0 + bias[0];
    out[o + 1024] = acc1 + bias[1];
    out[o + 2048] = acc2 + bias[2];
}

// ---------------------------------------------------------------------------
static GemmP mkP(const float* A, const float* W, const float* bias, const float* res,
                 float* out, const float* ascale, const float* aweight,
                 int N, int K, int IC, int IH, int IW, int OH, int OW,
                 int stride, int padh, int padw,
                 int oscale, int ooffh, int ooffw, int oW, int oHW, int mode) {
    GemmP p;
    p.A = A; p.W = W; p.bias = bias; p.res = res; p.out = out;
    p.ascale = ascale; p.aweight = aweight;
    p.N = N; p.K = K; p.IC = IC; p.IH = IH; p.IW = IW; p.OH = OH; p.OW = OW;
    p.stride = stride; p.padh = padh; p.padw = padw;
    p.oscale = oscale; p.ooffh = ooffh; p.ooffw = ooffw; p.oW = oW; p.oHW = oHW;
    p.mode = mode;
    return p;
}

template<int KH, int KW, bool RMS>
static void launch_bf16(GemmP p, int M) {
    dim3 g(M / 128, p.N / 128);
    conv_bf16<KH, KW, RMS, false><<<g, 256>>>(p);
}

static void res_block(float* x, float* tmp, float* scl, const float* rmsw,
                      const float* w3, const float* b3,
                      const float* w1, const float* b1) {
    rms_scale_kernel<<<256, 256>>>(x, scl);
    {
        GemmP p = mkP(x, w3, b3, x, tmp, scl, rmsw,
                      256, 2304, 256, 8, 8, 8, 8, 1, 1, 1,
                      1, 0, 0, 8, 64, 2);
        launch_bf16<3, 3, true>(p, 16384);
    }
    rms_scale_kernel<<<256, 256>>>(tmp, scl);
    {
        GemmP p = mkP(tmp, w1, b1, tmp, x, scl, rmsw + 16384,
                      256, 256, 256, 8, 8, 8, 8, 1, 0, 0,
                      1, 0, 0, 8, 64, 2);
        launch_bf16<1, 1, true>(p, 16384);
    }
}

extern "C" void kernel_launch(void* const* d_in, const int* in_sizes, int n_in,
                              void* d_out, int out_size) {
    const float* x       = (const float*)d_in[0];
    const float* enc_w1  = (const float*)d_in[1];
    const float* enc_b1  = (const float*)d_in[2];
    const float* enc_w2  = (const float*)d_in[3];
    const float* enc_b2  = (const float*)d_in[4];
    const float* rms_w   = (const float*)d_in[5];
    const float* c3_w    = (const float*)d_in[6];
    const float* c3_b    = (const float*)d_in[7];
    const float* c1_w    = (const float*)d_in[8];
    const float* c1_b    = (const float*)d_in[9];
    const float* emb     = (const float*)d_in[10];
    const float* dec_w1  = (const float*)d_in[11];
    const float* dec_b1  = (const float*)d_in[12];
    const float* dec_w2  = (const float*)d_in[13];
    const float* dec_b2  = (const float*)d_in[14];
    float* out = (float*)d_out;

    float *h16, *h8, *t8, *q, *scores, *wp, *en, *scl, *part;
    cudaGetSymbolAddress((void**)&h16, g_h16);
    cudaGetSymbolAddress((void**)&h8, g_h8);
    cudaGetSymbolAddress((void**)&t8, g_t8);
    cudaGetSymbolAddress((void**)&q, g_q);
    cudaGetSymbolAddress((void**)&scores, g_scores);
    cudaGetSymbolAddress((void**)&wp, g_wp);
    cudaGetSymbolAddress((void**)&en, g_enorm);
    cudaGetSymbolAddress((void**)&scl, g_scale);
    cudaGetSymbolAddress((void**)&part, g_part);

    // ---- Encoder ----
    {
        GemmP p = mkP(x, enc_w1, enc_b1, nullptr, h16, nullptr, nullptr,
                      256, 48, 3, 32, 32, 16, 16, 2, 1, 1,
                      1, 0, 0, 16, 256, 1);
        launch_bf16<4, 4, false>(p, 65536);
    }
    {
        GemmP p = mkP(h16, enc_w2, enc_b2, nullptr, h8, nullptr, nullptr,
                      256, 4096, 256, 16, 16, 8, 8, 2, 1, 1,
                      1, 0, 0, 8, 64, 1);
        launch_bf16<4, 4, false>(p, 16384);
    }
    res_block(h8, t8, scl, rms_w + 0 * 32768, c3_w + 0 * 589824, c3_b + 0 * 256,
              c1_w + 0 * 65536, c1_b + 0 * 256);
    res_block(h8, t8, scl, rms_w + 1 * 32768, c3_w + 1 * 589824, c3_b + 1 * 256,
              c1_w + 1 * 65536, c1_b + 1 * 256);

    // ---- VQ (scores via bf16x3 GEMM; argmin + q gather exact) ----
    enorm_kernel<<<2, 256>>>(emb, en);
    {
        GemmP p = mkP(h8, emb, nullptr, nullptr, scores, nullptr, nullptr,
                      512, 256, 256, 8, 8, 8, 8, 1, 0, 0,
                      1, 0, 0, 8, 64, 0);
        launch_bf16<1, 1, false>(p, 16384);
    }
    vq_argmin_kernel<<<2048, 256>>>(scores, en, emb, q);
    sqdiff_kernel<<<256, 256>>>(h8, q, part, 1048576);

    // ---- Decoder ----
    res_block(q, t8, scl, rms_w + 2 * 32768, c3_w + 2 * 589824, c3_b + 2 * 256,
              c1_w + 2 * 65536, c1_b + 2 * 256);
    res_block(q, t8, scl, rms_w + 3 * 32768, c3_w + 3 * 589824, c3_b + 3 * 256,
              c1_w + 3 * 65536, c1_b + 3 * 256);

    // deconv1: 4 parity GEMMs fused into one launch via grid.z
    prep_wp_kernel<<<4096, 256>>>(dec_w1, wp);
    {
        GemmP p = mkP(q, wp, dec_b1, nullptr, h16, nullptr, nullptr,
                      256, 1024, 256, 8, 8, 8, 8, 1, 0, 0,
                      2, 0, 0, 16, 256, 1);
        conv_bf16<2, 2, false, true><<<dim3(128, 2, 4), 256>>>(p);
    }

    deconv2_kernel<<<dim3(256, 4), 256>>>(h16, dec_w2, dec_b2, out + 4);

    sqdiff_kernel<<<256, 256>>>(out + 4, x, part + 256, 196608);
    finalize_kernel<<<1, 32>>>(part, part + 256, out);
}